// round 4
// baseline (speedup 1.0000x reference)
#include <cuda_runtime.h>
#include <cuda_bf16.h>
#include <cstdint>

#define EPS_VAL 1e-11f

// ---------------- scratch (__device__ globals; no allocs allowed) -----------
__device__ float g_q [4*16*2048*64];   // [B,H,S,dk]
__device__ float g_k [4*16*2048*64];
__device__ float g_v [4*16*2048*64];
__device__ float g_ao[4*2048*1024];    // [B,S,H*dk]
__device__ __nv_bfloat16 g_ahi[8192*1024];
__device__ __nv_bfloat16 g_alo[8192*1024];
__device__ __nv_bfloat16 g_whi[1024*1024];
__device__ __nv_bfloat16 g_wlo[1024*1024];

// ---------------- PTX helpers (generic ISA, valid at compute_103) -----------
__device__ __forceinline__ uint32_t smem_u32(const void* p) {
    uint32_t a;
    asm("{ .reg .u64 t; cvta.to.shared.u64 t, %1; cvt.u32.u64 %0, t; }"
        : "=r"(a) : "l"(p));
    return a;
}
__device__ __forceinline__ void cpa16(uint32_t dst, const void* src) {
    asm volatile("cp.async.cg.shared.global [%0], [%1], 16;"
                 :: "r"(dst), "l"(src) : "memory");
}
#define CP_COMMIT() asm volatile("cp.async.commit_group;" ::: "memory")
#define CP_WAIT(n)  asm volatile("cp.async.wait_group %0;" :: "n"(n) : "memory")

#define LDSM4(r0, r1, r2, r3, addr)                                          \
    asm volatile("ldmatrix.sync.aligned.m8n8.x4.shared.b16 {%0,%1,%2,%3}, [%4];" \
                 : "=r"(r0), "=r"(r1), "=r"(r2), "=r"(r3) : "r"(addr))

#define MMA16816(d, a, b)                                                    \
    asm volatile("mma.sync.aligned.m16n8k16.row.col.f32.bf16.bf16.f32 "      \
                 "{%0,%1,%2,%3}, {%4,%5,%6,%7}, {%8,%9}, {%0,%1,%2,%3};"     \
                 : "+f"((d)[0]), "+f"((d)[1]), "+f"((d)[2]), "+f"((d)[3])    \
                 : "r"((a)[0]), "r"((a)[1]), "r"((a)[2]), "r"((a)[3]),       \
                   "r"((b)[0]), "r"((b)[1]))

// ---------------- fp32 -> bf16 hi/lo split ----------------------------------
__device__ __forceinline__ uint32_t pack_bf2(__nv_bfloat16 a, __nv_bfloat16 b) {
    return (uint32_t)__bfloat16_as_ushort(a) |
           ((uint32_t)__bfloat16_as_ushort(b) << 16);
}
__global__ __launch_bounds__(256) void conv_split(
    const float4* __restrict__ src, uint2* __restrict__ hi,
    uint2* __restrict__ lo, int n4)
{
    int i = blockIdx.x * blockDim.x + threadIdx.x;
    if (i >= n4) return;
    float4 v = src[i];
    __nv_bfloat16 h0 = __float2bfloat16(v.x), h1 = __float2bfloat16(v.y);
    __nv_bfloat16 h2 = __float2bfloat16(v.z), h3 = __float2bfloat16(v.w);
    __nv_bfloat16 l0 = __float2bfloat16(v.x - __bfloat162float(h0));
    __nv_bfloat16 l1 = __float2bfloat16(v.y - __bfloat162float(h1));
    __nv_bfloat16 l2 = __float2bfloat16(v.z - __bfloat162float(h2));
    __nv_bfloat16 l3 = __float2bfloat16(v.w - __bfloat162float(h3));
    hi[i] = make_uint2(pack_bf2(h0, h1), pack_bf2(h2, h3));
    lo[i] = make_uint2(pack_bf2(l0, l1), pack_bf2(l2, l3));
}

// ---------------- bf16 hi/lo GEMM via mma.sync (HMMA) -----------------------
// C[8192,1024] = A @ W^T + bias,  D = Ah*Wh + Ah*Wl + Al*Wh  (fp32 accum)
// CTA tile 128x128, BK=64 bf16, 3-stage cp.async pipeline, SW128 swizzle.
// 8 warps (2x4), warptile 64x32. mode 0: scatter to [B,H,S,dk]; mode 1: row-major.
#define G_STAGES 3
#define G_MAT_BYTES 16384              // 128 rows x 128B
#define G_STAGE_BYTES (4 * G_MAT_BYTES)
#define G_SMEM (G_STAGES * G_STAGE_BYTES)

__device__ __forceinline__ void stage_load(
    uint32_t sb, const __nv_bfloat16* __restrict__ Ah,
    const __nv_bfloat16* __restrict__ Al, const __nv_bfloat16* __restrict__ Wh,
    const __nv_bfloat16* __restrict__ Wl, int kt, int tid)
{
    const __nv_bfloat16* srcs[4] = {Ah, Al, Wh, Wl};
    #pragma unroll
    for (int m = 0; m < 4; ++m) {
        uint32_t mb = sb + m * G_MAT_BYTES;
        const __nv_bfloat16* sp = srcs[m];
        #pragma unroll
        for (int i = 0; i < 4; ++i) {
            int seg = tid + (i << 8);
            int row = seg >> 3, cs = seg & 7;
            const void* src = sp + (size_t)row * 1024 + (kt << 6) + (cs << 3);
            uint32_t dst = mb + row * 128 + ((cs << 4) ^ ((row & 7) << 4));
            cpa16(dst, src);
        }
    }
    CP_COMMIT();
}

__global__ __launch_bounds__(256, 1) void gemm_tc(
    const __nv_bfloat16* __restrict__ Ahi, const __nv_bfloat16* __restrict__ Alo,
    const __nv_bfloat16* __restrict__ Whi, const __nv_bfloat16* __restrict__ Wlo,
    const float* __restrict__ bias, float* __restrict__ out, int mode)
{
    extern __shared__ __align__(128) char dynsm[];
    __shared__ float bias_s[128];

    const int tid  = threadIdx.x;
    const int wid  = tid >> 5;
    const int lane = tid & 31;
    const int m0 = blockIdx.y << 7;
    const int n0 = blockIdx.x << 7;
    const int wm = (wid >> 2) << 6;     // 0 or 64
    const int wn = (wid & 3) << 5;      // 0,32,64,96

    if (tid < 128) bias_s[tid] = bias[n0 + tid];

    const uint32_t sb0 = smem_u32(dynsm);
    const __nv_bfloat16* pAh = Ahi + (size_t)m0 * 1024;
    const __nv_bfloat16* pAl = Alo + (size_t)m0 * 1024;
    const __nv_bfloat16* pWh = Whi + (size_t)n0 * 1024;
    const __nv_bfloat16* pWl = Wlo + (size_t)n0 * 1024;

    stage_load(sb0,                  pAh, pAl, pWh, pWl, 0, tid);
    stage_load(sb0 + G_STAGE_BYTES,  pAh, pAl, pWh, pWl, 1, tid);
    stage_load(sb0 + 2*G_STAGE_BYTES,pAh, pAl, pWh, pWl, 2, tid);

    float acc[4][4][4] = {};
    const int lr = lane & 15;           // ldmatrix row-within-16
    const int lxh = (lane >> 4) << 4;   // 0 or 16 (byte half offset)

    for (int j = 0; j < 16; ++j) {
        if (j < 14)      CP_WAIT(2);
        else if (j == 14) CP_WAIT(1);
        else              CP_WAIT(0);
        __syncthreads();

        const uint32_t sb = sb0 + (j % 3) * G_STAGE_BYTES;
        #pragma unroll
        for (int kk = 0; kk < 4; ++kk) {
            const int x = (kk << 5) + lxh;
            uint32_t ah[4][4], al[4][4];
            #pragma unroll
            for (int mi = 0; mi < 4; ++mi) {
                int row = wm + (mi << 4) + lr;
                uint32_t ad = sb + row * 128 + (x ^ ((row & 7) << 4));
                LDSM4(ah[mi][0], ah[mi][1], ah[mi][2], ah[mi][3], ad);
                LDSM4(al[mi][0], al[mi][1], al[mi][2], al[mi][3],
                      ad + G_MAT_BYTES);
            }
            uint32_t whf[4][2], wlf[4][2];
            #pragma unroll
            for (int g = 0; g < 2; ++g) {
                int row = wn + (g << 4) + lr;
                uint32_t wd = sb + 2 * G_MAT_BYTES + row * 128 +
                              (x ^ ((row & 7) << 4));
                uint32_t r0, r1, r2, r3;
                LDSM4(r0, r1, r2, r3, wd);
                whf[g*2][0] = r0; whf[g*2][1] = r2;
                whf[g*2+1][0] = r1; whf[g*2+1][1] = r3;
                LDSM4(r0, r1, r2, r3, wd + G_MAT_BYTES);
                wlf[g*2][0] = r0; wlf[g*2][1] = r2;
                wlf[g*2+1][0] = r1; wlf[g*2+1][1] = r3;
            }
            #pragma unroll
            for (int mi = 0; mi < 4; ++mi)
                #pragma unroll
                for (int ni = 0; ni < 4; ++ni) {
                    MMA16816(acc[mi][ni], ah[mi], whf[ni]);
                    MMA16816(acc[mi][ni], ah[mi], wlf[ni]);
                    MMA16816(acc[mi][ni], al[mi], whf[ni]);
                }
        }
        __syncthreads();
        if (j + 3 < 16)
            stage_load(sb0 + (j % 3) * G_STAGE_BYTES, pAh, pAl, pWh, pWl,
                       j + 3, tid);
    }

    // ---------------- epilogue ----------------
    const int rbase = m0 + wm + (lane >> 2);
    const int cbase = n0 + wn + ((lane & 3) << 1);
    #pragma unroll
    for (int mi = 0; mi < 4; ++mi) {
        #pragma unroll
        for (int ni = 0; ni < 4; ++ni) {
            int col = cbase + (ni << 3);
            float b0 = bias_s[col - n0], b1 = bias_s[col - n0 + 1];
            #pragma unroll
            for (int half = 0; half < 2; ++half) {
                int row = rbase + (mi << 4) + (half << 3);
                float2 v = make_float2(acc[mi][ni][half*2]   + b0,
                                       acc[mi][ni][half*2+1] + b1);
                if (mode == 0) {
                    int h = col >> 6, d = col & 63;
                    int b = row >> 11, s = row & 2047;
                    *reinterpret_cast<float2*>(
                        &out[((size_t)((b << 4) + h) * 2048 + s) * 64 + d]) = v;
                } else {
                    *reinterpret_cast<float2*>(
                        &out[(size_t)row * 1024 + col]) = v;
                }
            }
        }
    }
}

// ---------------- flash attention (fp32, unchanged from R1) -----------------
__global__ __launch_bounds__(256) void attn_kernel(const int* __restrict__ mask)
{
    extern __shared__ float sm[];
    float* Qts = sm;
    float* Kts = Qts + 64 * 68;
    float* Vsm = Kts + 64 * 68;
    float* Psm = Vsm + 64 * 68;
    int*   Msm = reinterpret_cast<int*>(Psm + 64 * 68);

    const int tid = threadIdx.x;
    const int tx = tid & 15, ty = tid >> 4;
    const int bh = blockIdx.y;
    const int b = bh >> 4, h = bh & 15;
    const int q0 = blockIdx.x << 6;

    const float* Qg = g_q + (size_t)bh * 2048 * 64;
    const float* Kg = g_k + (size_t)bh * 2048 * 64;
    const float* Vg = g_v + (size_t)bh * 2048 * 64;
    const int*   Mg = mask + (size_t)b * 2048 * 2048;

    #pragma unroll
    for (int i = 0; i < 4; ++i) {
        int idx = tid + (i << 8);
        int r = idx >> 4, c = (idx & 15) << 2;
        float4 qv = *reinterpret_cast<const float4*>(Qg + (size_t)(q0 + r) * 64 + c);
        Qts[(c+0)*68 + r] = qv.x;
        Qts[(c+1)*68 + r] = qv.y;
        Qts[(c+2)*68 + r] = qv.z;
        Qts[(c+3)*68 + r] = qv.w;
    }

    float o[4][4] = {};
    float mrow[4] = {-1e30f, -1e30f, -1e30f, -1e30f};
    float lrow[4] = {};

    for (int k0 = 0; k0 < 2048; k0 += 64) {
        __syncthreads();
        #pragma unroll
        for (int i = 0; i < 4; ++i) {
            int idx = tid + (i << 8);
            int r = idx >> 4, c = (idx & 15) << 2;
            float4 kv = *reinterpret_cast<const float4*>(Kg + (size_t)(k0 + r) * 64 + c);
            Kts[(c+0)*68 + r] = kv.x;
            Kts[(c+1)*68 + r] = kv.y;
            Kts[(c+2)*68 + r] = kv.z;
            Kts[(c+3)*68 + r] = kv.w;
            float4 vv = *reinterpret_cast<const float4*>(Vg + (size_t)(k0 + r) * 64 + c);
            *reinterpret_cast<float4*>(&Vsm[r*68 + c]) = vv;
            int4 mv = *reinterpret_cast<const int4*>(Mg + (size_t)(q0 + r) * 2048 + k0 + c);
            *reinterpret_cast<int4*>(&Msm[r*68 + c]) = mv;
        }
        __syncthreads();

        float sc[4][4] = {};
        #pragma unroll 8
        for (int d = 0; d < 64; ++d) {
            float4 q4 = *reinterpret_cast<const float4*>(&Qts[d*68 + (ty << 2)]);
            float4 k4 = *reinterpret_cast<const float4*>(&Kts[d*68 + (tx << 2)]);
            float qa[4] = {q4.x, q4.y, q4.z, q4.w};
            float ka[4] = {k4.x, k4.y, k4.z, k4.w};
            #pragma unroll
            for (int i = 0; i < 4; ++i)
                #pragma unroll
                for (int j = 0; j < 4; ++j)
                    sc[i][j] = fmaf(qa[i], ka[j], sc[i][j]);
        }

        #pragma unroll
        for (int i = 0; i < 4; ++i) {
            const int qr = (ty << 2) + i;
            float p[4];
            #pragma unroll
            for (int j = 0; j < 4; ++j) {
                int mk = Msm[qr*68 + (tx << 2) + j];
                p[j] = (mk == 0) ? EPS_VAL : sc[i][j] * 0.125f;
            }
            float tm = fmaxf(fmaxf(p[0], p[1]), fmaxf(p[2], p[3]));
            #pragma unroll
            for (int off = 8; off > 0; off >>= 1)
                tm = fmaxf(tm, __shfl_xor_sync(0xffffffffu, tm, off));
            float mn = fmaxf(mrow[i], tm);
            float corr = __expf(mrow[i] - mn);
            float rs = 0.f;
            #pragma unroll
            for (int j = 0; j < 4; ++j) {
                float e = __expf(p[j] - mn);
                Psm[qr*68 + (tx << 2) + j] = e;
                rs += e;
            }
            #pragma unroll
            for (int off = 8; off > 0; off >>= 1)
                rs += __shfl_xor_sync(0xffffffffu, rs, off);
            lrow[i] = lrow[i] * corr + rs;
            mrow[i] = mn;
            #pragma unroll
            for (int j = 0; j < 4; ++j) o[i][j] *= corr;
        }
        __syncthreads();

        #pragma unroll 4
        for (int k = 0; k < 64; k += 4) {
            float4 pv[4], vv[4];
            #pragma unroll
            for (int i = 0; i < 4; ++i)
                pv[i] = *reinterpret_cast<const float4*>(&Psm[((ty << 2) + i)*68 + k]);
            #pragma unroll
            for (int e = 0; e < 4; ++e)
                vv[e] = *reinterpret_cast<const float4*>(&Vsm[(k + e)*68 + (tx << 2)]);
            #pragma unroll
            for (int i = 0; i < 4; ++i) {
                float pa[4] = {pv[i].x, pv[i].y, pv[i].z, pv[i].w};
                #pragma unroll
                for (int e = 0; e < 4; ++e) {
                    o[i][0] = fmaf(pa[e], vv[e].x, o[i][0]);
                    o[i][1] = fmaf(pa[e], vv[e].y, o[i][1]);
                    o[i][2] = fmaf(pa[e], vv[e].z, o[i][2]);
                    o[i][3] = fmaf(pa[e], vv[e].w, o[i][3]);
                }
            }
        }
    }

    #pragma unroll
    for (int i = 0; i < 4; ++i) {
        float inv = 1.f / lrow[i];
        int q = q0 + (ty << 2) + i;
        float4 r = make_float4(o[i][0]*inv, o[i][1]*inv, o[i][2]*inv, o[i][3]*inv);
        *reinterpret_cast<float4*>(
            &g_ao[((size_t)(b * 2048 + q)) * 1024 + h * 64 + (tx << 2)]) = r;
    }
}

// ---------------------------------------------------------------------------
extern "C" void kernel_launch(void* const* d_in, const int* in_sizes, int n_in,
                              void* d_out, int out_size)
{
    const float* query = (const float*)d_in[0];
    const float* key_  = (const float*)d_in[1];
    const float* value = (const float*)d_in[2];
    const int*   mask  = (const int*)  d_in[3];
    const float* wq = (const float*)d_in[4];
    const float* bq = (const float*)d_in[5];
    const float* wk = (const float*)d_in[6];
    const float* bk = (const float*)d_in[7];
    const float* wv = (const float*)d_in[8];
    const float* bv = (const float*)d_in[9];
    const float* wo = (const float*)d_in[10];
    const float* bo = (const float*)d_in[11];

    float *pq, *pk, *pv, *pao;
    __nv_bfloat16 *pahi, *palo, *pwhi, *pwlo;
    cudaGetSymbolAddress((void**)&pq,   g_q);
    cudaGetSymbolAddress((void**)&pk,   g_k);
    cudaGetSymbolAddress((void**)&pv,   g_v);
    cudaGetSymbolAddress((void**)&pao,  g_ao);
    cudaGetSymbolAddress((void**)&pahi, g_ahi);
    cudaGetSymbolAddress((void**)&palo, g_alo);
    cudaGetSymbolAddress((void**)&pwhi, g_whi);
    cudaGetSymbolAddress((void**)&pwlo, g_wlo);

    cudaFuncSetAttribute(gemm_tc,
                         cudaFuncAttributeMaxDynamicSharedMemorySize, G_SMEM);
    const int attn_smem = 5 * 64 * 68 * 4;
    cudaFuncSetAttribute(attn_kernel,
                         cudaFuncAttributeMaxDynamicSharedMemorySize, attn_smem);

    #define PROJ(Asrc, Wsrc, Bsrc, Odst, MODE)                                \
        conv_split<<<8192, 256>>>((const float4*)(Asrc), (uint2*)pahi,        \
                                  (uint2*)palo, 2097152);                     \
        conv_split<<<1024, 256>>>((const float4*)(Wsrc), (uint2*)pwhi,        \
                                  (uint2*)pwlo, 262144);                      \
        gemm_tc<<<dim3(8, 64), 256, G_SMEM>>>(pahi, palo, pwhi, pwlo,         \
                                              (Bsrc), (Odst), (MODE));

    PROJ(query, wq, bq, pq, 0)
    PROJ(key_,  wk, bk, pk, 0)
    PROJ(value, wv, bv, pv, 0)

    attn_kernel<<<dim3(32, 64), 256, attn_smem>>>(mask);

    PROJ(pao, wo, bo, (float*)d_out, 1)
    #undef PROJ
}

// round 5
// speedup vs baseline: 2.0468x; 2.0468x over previous
#include <cuda_runtime.h>
#include <cuda_bf16.h>
#include <cstdint>

#define EPS_VAL 1e-11f

// ---------------- scratch (__device__ globals; no allocs allowed) -----------
__device__ __nv_bfloat16 g_qhi[4*16*2048*64];  // [B,H,S,dk]
__device__ __nv_bfloat16 g_qlo[4*16*2048*64];
__device__ __nv_bfloat16 g_khi[4*16*2048*64];
__device__ __nv_bfloat16 g_klo[4*16*2048*64];
__device__ __nv_bfloat16 g_vhi[4*16*2048*64];
__device__ __nv_bfloat16 g_vlo[4*16*2048*64];
__device__ __nv_bfloat16 g_ahi[8192*1024];     // GEMM A input / attn out (hi)
__device__ __nv_bfloat16 g_alo[8192*1024];
__device__ __nv_bfloat16 g_whi[1024*1024];
__device__ __nv_bfloat16 g_wlo[1024*1024];
__device__ unsigned char g_m8[4*2048*2048];    // int8 mask

// ---------------- PTX helpers (generic ISA, valid at compute_103) -----------
__device__ __forceinline__ uint32_t smem_u32(const void* p) {
    uint32_t a;
    asm("{ .reg .u64 t; cvta.to.shared.u64 t, %1; cvt.u32.u64 %0, t; }"
        : "=r"(a) : "l"(p));
    return a;
}
__device__ __forceinline__ void cpa16(uint32_t dst, const void* src) {
    asm volatile("cp.async.cg.shared.global [%0], [%1], 16;"
                 :: "r"(dst), "l"(src) : "memory");
}
#define CP_COMMIT() asm volatile("cp.async.commit_group;" ::: "memory")
#define CP_WAIT(n)  asm volatile("cp.async.wait_group %0;" :: "n"(n) : "memory")

#define LDSM4(r0, r1, r2, r3, addr)                                          \
    asm volatile("ldmatrix.sync.aligned.m8n8.x4.shared.b16 {%0,%1,%2,%3}, [%4];" \
                 : "=r"(r0), "=r"(r1), "=r"(r2), "=r"(r3) : "r"(addr))
#define LDSM4T(r0, r1, r2, r3, addr)                                         \
    asm volatile("ldmatrix.sync.aligned.m8n8.x4.trans.shared.b16 {%0,%1,%2,%3}, [%4];" \
                 : "=r"(r0), "=r"(r1), "=r"(r2), "=r"(r3) : "r"(addr))

#define MMA16816(d, a, b)                                                    \
    asm volatile("mma.sync.aligned.m16n8k16.row.col.f32.bf16.bf16.f32 "      \
                 "{%0,%1,%2,%3}, {%4,%5,%6,%7}, {%8,%9}, {%0,%1,%2,%3};"     \
                 : "+f"((d)[0]), "+f"((d)[1]), "+f"((d)[2]), "+f"((d)[3])    \
                 : "r"((a)[0]), "r"((a)[1]), "r"((a)[2]), "r"((a)[3]),       \
                   "r"((b)[0]), "r"((b)[1]))

__device__ __forceinline__ uint32_t pack_bf2(__nv_bfloat16 a, __nv_bfloat16 b) {
    return (uint32_t)__bfloat16_as_ushort(a) |
           ((uint32_t)__bfloat16_as_ushort(b) << 16);
}

// ---------------- conversions ------------------------------------------------
__global__ __launch_bounds__(256) void conv_split(
    const float4* __restrict__ src, uint2* __restrict__ hi,
    uint2* __restrict__ lo, int n4)
{
    int i = blockIdx.x * blockDim.x + threadIdx.x;
    if (i >= n4) return;
    float4 v = src[i];
    __nv_bfloat16 h0 = __float2bfloat16(v.x), h1 = __float2bfloat16(v.y);
    __nv_bfloat16 h2 = __float2bfloat16(v.z), h3 = __float2bfloat16(v.w);
    __nv_bfloat16 l0 = __float2bfloat16(v.x - __bfloat162float(h0));
    __nv_bfloat16 l1 = __float2bfloat16(v.y - __bfloat162float(h1));
    __nv_bfloat16 l2 = __float2bfloat16(v.z - __bfloat162float(h2));
    __nv_bfloat16 l3 = __float2bfloat16(v.w - __bfloat162float(h3));
    hi[i] = make_uint2(pack_bf2(h0, h1), pack_bf2(h2, h3));
    lo[i] = make_uint2(pack_bf2(l0, l1), pack_bf2(l2, l3));
}

__global__ __launch_bounds__(256) void conv_mask(
    const int4* __restrict__ src, uchar4* __restrict__ dst, int n4)
{
    int i = blockIdx.x * blockDim.x + threadIdx.x;
    if (i >= n4) return;
    int4 v = src[i];
    dst[i] = make_uchar4((unsigned char)v.x, (unsigned char)v.y,
                         (unsigned char)v.z, (unsigned char)v.w);
}

// ---------------- bf16 hi/lo GEMM via mma.sync (HMMA) -----------------------
// C[8192,1024] = A @ W^T + bias.  mode 0: write bf16 hi/lo scattered to
// [B,H,S,dk]; mode 1: fp32 row-major (final output).
#define G_STAGES 3
#define G_MAT_BYTES 16384
#define G_STAGE_BYTES (4 * G_MAT_BYTES)
#define G_SMEM (G_STAGES * G_STAGE_BYTES)

__device__ __forceinline__ void stage_load(
    uint32_t sb, const __nv_bfloat16* __restrict__ Ah,
    const __nv_bfloat16* __restrict__ Al, const __nv_bfloat16* __restrict__ Wh,
    const __nv_bfloat16* __restrict__ Wl, int kt, int tid)
{
    const __nv_bfloat16* srcs[4] = {Ah, Al, Wh, Wl};
    #pragma unroll
    for (int m = 0; m < 4; ++m) {
        uint32_t mb = sb + m * G_MAT_BYTES;
        const __nv_bfloat16* sp = srcs[m];
        #pragma unroll
        for (int i = 0; i < 4; ++i) {
            int seg = tid + (i << 8);
            int row = seg >> 3, cs = seg & 7;
            const void* src = sp + (size_t)row * 1024 + (kt << 6) + (cs << 3);
            uint32_t dst = mb + row * 128 + ((cs << 4) ^ ((row & 7) << 4));
            cpa16(dst, src);
        }
    }
    CP_COMMIT();
}

__global__ __launch_bounds__(256, 1) void gemm_tc(
    const __nv_bfloat16* __restrict__ Ahi, const __nv_bfloat16* __restrict__ Alo,
    const __nv_bfloat16* __restrict__ Whi, const __nv_bfloat16* __restrict__ Wlo,
    const float* __restrict__ bias, float* __restrict__ outf,
    __nv_bfloat16* __restrict__ outh, __nv_bfloat16* __restrict__ outl, int mode)
{
    extern __shared__ __align__(128) char dynsm[];
    __shared__ float bias_s[128];

    const int tid  = threadIdx.x;
    const int wid  = tid >> 5;
    const int lane = tid & 31;
    const int m0 = blockIdx.y << 7;
    const int n0 = blockIdx.x << 7;
    const int wm = (wid >> 2) << 6;
    const int wn = (wid & 3) << 5;

    if (tid < 128) bias_s[tid] = bias[n0 + tid];

    const uint32_t sb0 = smem_u32(dynsm);
    const __nv_bfloat16* pAh = Ahi + (size_t)m0 * 1024;
    const __nv_bfloat16* pAl = Alo + (size_t)m0 * 1024;
    const __nv_bfloat16* pWh = Whi + (size_t)n0 * 1024;
    const __nv_bfloat16* pWl = Wlo + (size_t)n0 * 1024;

    stage_load(sb0,                   pAh, pAl, pWh, pWl, 0, tid);
    stage_load(sb0 + G_STAGE_BYTES,   pAh, pAl, pWh, pWl, 1, tid);
    stage_load(sb0 + 2*G_STAGE_BYTES, pAh, pAl, pWh, pWl, 2, tid);

    float acc[4][4][4] = {};
    const int lr = lane & 15;
    const int lxh = (lane >> 4) << 4;

    for (int j = 0; j < 16; ++j) {
        if (j < 14)      CP_WAIT(2);
        else if (j == 14) CP_WAIT(1);
        else              CP_WAIT(0);
        __syncthreads();

        const uint32_t sb = sb0 + (j % 3) * G_STAGE_BYTES;
        #pragma unroll
        for (int kk = 0; kk < 4; ++kk) {
            const int x = (kk << 5) + lxh;
            uint32_t ah[4][4], al[4][4];
            #pragma unroll
            for (int mi = 0; mi < 4; ++mi) {
                int row = wm + (mi << 4) + lr;
                uint32_t ad = sb + row * 128 + (x ^ ((row & 7) << 4));
                LDSM4(ah[mi][0], ah[mi][1], ah[mi][2], ah[mi][3], ad);
                LDSM4(al[mi][0], al[mi][1], al[mi][2], al[mi][3],
                      ad + G_MAT_BYTES);
            }
            uint32_t whf[4][2], wlf[4][2];
            #pragma unroll
            for (int g = 0; g < 2; ++g) {
                int row = wn + (g << 4) + lr;
                uint32_t wd = sb + 2 * G_MAT_BYTES + row * 128 +
                              (x ^ ((row & 7) << 4));
                uint32_t r0, r1, r2, r3;
                LDSM4(r0, r1, r2, r3, wd);
                whf[g*2][0] = r0; whf[g*2][1] = r2;
                whf[g*2+1][0] = r1; whf[g*2+1][1] = r3;
                LDSM4(r0, r1, r2, r3, wd + G_MAT_BYTES);
                wlf[g*2][0] = r0; wlf[g*2][1] = r2;
                wlf[g*2+1][0] = r1; wlf[g*2+1][1] = r3;
            }
            #pragma unroll
            for (int mi = 0; mi < 4; ++mi)
                #pragma unroll
                for (int ni = 0; ni < 4; ++ni) {
                    MMA16816(acc[mi][ni], ah[mi], whf[ni]);
                    MMA16816(acc[mi][ni], ah[mi], wlf[ni]);
                    MMA16816(acc[mi][ni], al[mi], whf[ni]);
                }
        }
        __syncthreads();
        if (j + 3 < 16)
            stage_load(sb0 + (j % 3) * G_STAGE_BYTES, pAh, pAl, pWh, pWl,
                       j + 3, tid);
    }

    const int rbase = m0 + wm + (lane >> 2);
    const int cbase = n0 + wn + ((lane & 3) << 1);
    #pragma unroll
    for (int mi = 0; mi < 4; ++mi) {
        #pragma unroll
        for (int ni = 0; ni < 4; ++ni) {
            int col = cbase + (ni << 3);
            float b0 = bias_s[col - n0], b1 = bias_s[col - n0 + 1];
            #pragma unroll
            for (int half = 0; half < 2; ++half) {
                int row = rbase + (mi << 4) + (half << 3);
                float v0 = acc[mi][ni][half*2]   + b0;
                float v1 = acc[mi][ni][half*2+1] + b1;
                if (mode == 0) {
                    int h = col >> 6, d = col & 63;
                    int bb = row >> 11, s = row & 2047;
                    size_t idx = ((size_t)((bb << 4) + h) * 2048 + s) * 64 + d;
                    __nv_bfloat16 h0 = __float2bfloat16(v0);
                    __nv_bfloat16 h1 = __float2bfloat16(v1);
                    __nv_bfloat16 l0 = __float2bfloat16(v0 - __bfloat162float(h0));
                    __nv_bfloat16 l1 = __float2bfloat16(v1 - __bfloat162float(h1));
                    *reinterpret_cast<uint32_t*>(&outh[idx]) = pack_bf2(h0, h1);
                    *reinterpret_cast<uint32_t*>(&outl[idx]) = pack_bf2(l0, l1);
                } else {
                    *reinterpret_cast<float2*>(&outf[(size_t)row * 1024 + col]) =
                        make_float2(v0, v1);
                }
            }
        }
    }
}

// ---------------- tensor-core flash attention --------------------------------
// CTA: 128 q-rows of one (b,h); 8 warps x 16 q-rows. K-loop: 16 tiles of 128.
// QK^T and PV both 3-term bf16 hi/lo. P stays in registers (acc->A frag).
#define ATT_KV_BYTES 16384                    // 128 x 64 bf16
#define ATT_M_PITCH 144
#define ATT_M_BYTES (128 * ATT_M_PITCH)       // 18432
#define ATT_STAGE_BYTES (4*ATT_KV_BYTES + ATT_M_BYTES)   // 83968
#define ATT_SMEM (2*ATT_KV_BYTES + 2*ATT_STAGE_BYTES)    // 200704

__device__ __forceinline__ void att_stage(
    uint32_t sb, const __nv_bfloat16* __restrict__ K,
    const __nv_bfloat16* __restrict__ Kl, const __nv_bfloat16* __restrict__ V,
    const __nv_bfloat16* __restrict__ Vl, const unsigned char* __restrict__ M,
    int k0, int q0, int tid)
{
    #pragma unroll
    for (int i = 0; i < 4; ++i) {
        int seg = tid + (i << 8);
        int row = seg >> 3, cs = seg & 7;
        uint32_t so = row * 128 + ((cs << 4) ^ ((row & 7) << 4));
        size_t gofs = (size_t)(k0 + row) * 64 + (cs << 3);
        cpa16(sb + so,                 K  + gofs);
        cpa16(sb + ATT_KV_BYTES + so,  Kl + gofs);
        cpa16(sb + 2*ATT_KV_BYTES + so, V + gofs);
        cpa16(sb + 3*ATT_KV_BYTES + so, Vl + gofs);
        // mask tile (pitch 144, no swizzle)
        cpa16(sb + 4*ATT_KV_BYTES + row * ATT_M_PITCH + (cs << 4),
              M + (size_t)(q0 + row) * 2048 + k0 + (cs << 4));
    }
    CP_COMMIT();
}

__global__ __launch_bounds__(256, 1) void attn_tc(
    const __nv_bfloat16* __restrict__ qhi, const __nv_bfloat16* __restrict__ qlo,
    const __nv_bfloat16* __restrict__ khi, const __nv_bfloat16* __restrict__ klo,
    const __nv_bfloat16* __restrict__ vhi, const __nv_bfloat16* __restrict__ vlo,
    const unsigned char* __restrict__ m8,
    __nv_bfloat16* __restrict__ ohi, __nv_bfloat16* __restrict__ olo)
{
    extern __shared__ __align__(128) char sm[];
    const int tid  = threadIdx.x;
    const int wid  = tid >> 5;
    const int lane = tid & 31;
    const int bh = blockIdx.y;
    const int b = bh >> 4, h = bh & 15;
    const int q0 = blockIdx.x << 7;

    const uint32_t smb = smem_u32(sm);
    const uint32_t stg[2] = {smb + 2*ATT_KV_BYTES,
                             smb + 2*ATT_KV_BYTES + ATT_STAGE_BYTES};

    const size_t hofs = (size_t)bh * 2048 * 64;
    const __nv_bfloat16* gq  = qhi + hofs + (size_t)q0 * 64;
    const __nv_bfloat16* gql = qlo + hofs + (size_t)q0 * 64;
    const __nv_bfloat16* gk  = khi + hofs;
    const __nv_bfloat16* gkl = klo + hofs;
    const __nv_bfloat16* gv  = vhi + hofs;
    const __nv_bfloat16* gvl = vlo + hofs;
    const unsigned char* gm  = m8 + (size_t)b * 2048 * 2048;

    // Q tiles (hi, lo) -> smem, committed first
    #pragma unroll
    for (int i = 0; i < 4; ++i) {
        int seg = tid + (i << 8);
        int row = seg >> 3, cs = seg & 7;
        uint32_t so = row * 128 + ((cs << 4) ^ ((row & 7) << 4));
        size_t gofs = (size_t)row * 64 + (cs << 3);
        cpa16(smb + so,                gq  + gofs);
        cpa16(smb + ATT_KV_BYTES + so, gql + gofs);
    }
    CP_COMMIT();
    att_stage(stg[0], gk, gkl, gv, gvl, gm, 0,   q0, tid);
    att_stage(stg[1], gk, gkl, gv, gvl, gm, 128, q0, tid);

    CP_WAIT(2);
    __syncthreads();

    const int lr  = lane & 15;
    const int lxh = (lane >> 4) << 4;
    const int r   = lane >> 2;          // 0..7
    const int c2  = (lane & 3) << 1;    // 0,2,4,6

    // Q fragments (persistent)
    uint32_t qh[4][4], ql[4][4];
    {
        int row = (wid << 4) + lr;
        uint32_t rb = smb + row * 128;
        uint32_t sw = (row & 7) << 4;
        #pragma unroll
        for (int kk = 0; kk < 4; ++kk) {
            uint32_t ad = rb + (((kk << 5) + lxh) ^ sw);
            LDSM4(qh[kk][0], qh[kk][1], qh[kk][2], qh[kk][3], ad);
            LDSM4(ql[kk][0], ql[kk][1], ql[kk][2], ql[kk][3], ad + ATT_KV_BYTES);
        }
    }

    float o[8][4] = {};
    float m0 = -1e30f, m1 = -1e30f, l0 = 0.f, l1 = 0.f;
    const int qr0 = (wid << 4) + r;     // mask row (local)
    const char* msm_rel[2] = {sm + 2*ATT_KV_BYTES + 4*ATT_KV_BYTES,
                              sm + 2*ATT_KV_BYTES + ATT_STAGE_BYTES + 4*ATT_KV_BYTES};

    for (int kt = 0; kt < 16; ++kt) {
        if (kt < 15) { CP_WAIT(1); } else { CP_WAIT(0); }
        __syncthreads();
        const uint32_t sb = stg[kt & 1];
        const char* msk = msm_rel[kt & 1];

        // ---- S = Q K^T (3-term) ----
        float sc[16][4];
        #pragma unroll
        for (int nt = 0; nt < 16; ++nt)
            #pragma unroll
            for (int j = 0; j < 4; ++j) sc[nt][j] = 0.f;

        #pragma unroll
        for (int g = 0; g < 8; ++g) {
            int krow = (g << 4) + lr;
            uint32_t rb = sb + krow * 128;
            uint32_t sw = (krow & 7) << 4;
            #pragma unroll
            for (int kk = 0; kk < 4; ++kk) {
                uint32_t ad = rb + (((kk << 5) + lxh) ^ sw);
                uint32_t h0, h1, h2, h3, L0, L1, L2, L3;
                LDSM4(h0, h1, h2, h3, ad);
                LDSM4(L0, L1, L2, L3, ad + ATT_KV_BYTES);
                uint32_t bhE[2] = {h0, h2}, bhO[2] = {h1, h3};
                uint32_t blE[2] = {L0, L2}, blO[2] = {L1, L3};
                MMA16816(sc[2*g],   qh[kk], bhE);
                MMA16816(sc[2*g],   qh[kk], blE);
                MMA16816(sc[2*g],   ql[kk], bhE);
                MMA16816(sc[2*g+1], qh[kk], bhO);
                MMA16816(sc[2*g+1], qh[kk], blO);
                MMA16816(sc[2*g+1], ql[kk], bhO);
            }
        }

        // ---- scale + mask + online softmax ----
        float mx0 = -1e30f, mx1 = -1e30f;
        #pragma unroll
        for (int nt = 0; nt < 16; ++nt) {
            const unsigned char* mr0 = (const unsigned char*)
                (msk + qr0 * ATT_M_PITCH + (nt << 3) + c2);
            const unsigned char* mr1 = mr0 + 8 * ATT_M_PITCH;
            float v;
            v = mr0[0] ? sc[nt][0] * 0.125f : EPS_VAL; sc[nt][0] = v; mx0 = fmaxf(mx0, v);
            v = mr0[1] ? sc[nt][1] * 0.125f : EPS_VAL; sc[nt][1] = v; mx0 = fmaxf(mx0, v);
            v = mr1[0] ? sc[nt][2] * 0.125f : EPS_VAL; sc[nt][2] = v; mx1 = fmaxf(mx1, v);
            v = mr1[1] ? sc[nt][3] * 0.125f : EPS_VAL; sc[nt][3] = v; mx1 = fmaxf(mx1, v);
        }
        mx0 = fmaxf(mx0, __shfl_xor_sync(~0u, mx0, 1));
        mx0 = fmaxf(mx0, __shfl_xor_sync(~0u, mx0, 2));
        mx1 = fmaxf(mx1, __shfl_xor_sync(~0u, mx1, 1));
        mx1 = fmaxf(mx1, __shfl_xor_sync(~0u, mx1, 2));
        float mn0 = fmaxf(m0, mx0), mn1 = fmaxf(m1, mx1);
        float co0 = __expf(m0 - mn0), co1 = __expf(m1 - mn1);
        m0 = mn0; m1 = mn1;

        float rs0 = 0.f, rs1 = 0.f;
        #pragma unroll
        for (int nt = 0; nt < 16; ++nt) {
            float e;
            e = __expf(sc[nt][0] - mn0); sc[nt][0] = e; rs0 += e;
            e = __expf(sc[nt][1] - mn0); sc[nt][1] = e; rs0 += e;
            e = __expf(sc[nt][2] - mn1); sc[nt][2] = e; rs1 += e;
            e = __expf(sc[nt][3] - mn1); sc[nt][3] = e; rs1 += e;
        }
        rs0 += __shfl_xor_sync(~0u, rs0, 1); rs0 += __shfl_xor_sync(~0u, rs0, 2);
        rs1 += __shfl_xor_sync(~0u, rs1, 1); rs1 += __shfl_xor_sync(~0u, rs1, 2);
        l0 = l0 * co0 + rs0;
        l1 = l1 * co1 + rs1;
        #pragma unroll
        for (int ni = 0; ni < 8; ++ni) {
            o[ni][0] *= co0; o[ni][1] *= co0;
            o[ni][2] *= co1; o[ni][3] *= co1;
        }

        // ---- O += P V (3-term), P packed from accumulators ----
        #pragma unroll
        for (int t = 0; t < 8; ++t) {
            uint32_t aPh[4], aPl[4];
            #pragma unroll
            for (int u = 0; u < 4; ++u) {
                float p0 = sc[2*t + (u >> 1)][(u & 1) * 2];
                float p1 = sc[2*t + (u >> 1)][(u & 1) * 2 + 1];
                __nv_bfloat16 h0 = __float2bfloat16(p0);
                __nv_bfloat16 h1 = __float2bfloat16(p1);
                aPh[u] = pack_bf2(h0, h1);
                aPl[u] = pack_bf2(
                    __float2bfloat16(p0 - __bfloat162float(h0)),
                    __float2bfloat16(p1 - __bfloat162float(h1)));
            }
            int vrow = (t << 4) + lr;
            uint32_t rb = sb + 2*ATT_KV_BYTES + vrow * 128;
            uint32_t sw = (vrow & 7) << 4;
            #pragma unroll
            for (int dp = 0; dp < 4; ++dp) {
                uint32_t ad = rb + (((dp << 5) + lxh) ^ sw);
                uint32_t h0, h1, h2, h3, L0, L1, L2, L3;
                LDSM4T(h0, h1, h2, h3, ad);
                LDSM4T(L0, L1, L2, L3, ad + ATT_KV_BYTES);
                uint32_t bh0[2] = {h0, h1}, bh1[2] = {h2, h3};
                uint32_t bl0[2] = {L0, L1}, bl1[2] = {L2, L3};
                MMA16816(o[2*dp],   aPh, bh0);
                MMA16816(o[2*dp],   aPh, bl0);
                MMA16816(o[2*dp],   aPl, bh0);
                MMA16816(o[2*dp+1], aPh, bh1);
                MMA16816(o[2*dp+1], aPh, bl1);
                MMA16816(o[2*dp+1], aPl, bh1);
            }
        }

        __syncthreads();
        if (kt + 2 < 16)
            att_stage(stg[kt & 1], gk, gkl, gv, gvl, gm, (kt + 2) << 7, q0, tid);
    }

    // ---- epilogue: normalize, split hi/lo, store [B,S,1024] ----
    float i0 = 1.f / l0, i1 = 1.f / l1;
    int row0 = q0 + (wid << 4) + r;
    size_t base0 = ((size_t)(b * 2048) + row0) * 1024 + h * 64;
    size_t base1 = base0 + 8 * 1024;
    #pragma unroll
    for (int ni = 0; ni < 8; ++ni) {
        int d = (ni << 3) + c2;
        float v0 = o[ni][0] * i0, v1 = o[ni][1] * i0;
        float w0 = o[ni][2] * i1, w1 = o[ni][3] * i1;
        __nv_bfloat16 h0 = __float2bfloat16(v0), h1 = __float2bfloat16(v1);
        __nv_bfloat16 g0 = __float2bfloat16(w0), g1 = __float2bfloat16(w1);
        *reinterpret_cast<uint32_t*>(&ohi[base0 + d]) = pack_bf2(h0, h1);
        *reinterpret_cast<uint32_t*>(&olo[base0 + d]) = pack_bf2(
            __float2bfloat16(v0 - __bfloat162float(h0)),
            __float2bfloat16(v1 - __bfloat162float(h1)));
        *reinterpret_cast<uint32_t*>(&ohi[base1 + d]) = pack_bf2(g0, g1);
        *reinterpret_cast<uint32_t*>(&olo[base1 + d]) = pack_bf2(
            __float2bfloat16(w0 - __bfloat162float(g0)),
            __float2bfloat16(w1 - __bfloat162float(g1)));
    }
}

// ---------------------------------------------------------------------------
extern "C" void kernel_launch(void* const* d_in, const int* in_sizes, int n_in,
                              void* d_out, int out_size)
{
    const float* query = (const float*)d_in[0];
    const float* key_  = (const float*)d_in[1];
    const float* value = (const float*)d_in[2];
    const int*   mask  = (const int*)  d_in[3];
    const float* wq = (const float*)d_in[4];
    const float* bq = (const float*)d_in[5];
    const float* wk = (const float*)d_in[6];
    const float* bk = (const float*)d_in[7];
    const float* wv = (const float*)d_in[8];
    const float* bv = (const float*)d_in[9];
    const float* wo = (const float*)d_in[10];
    const float* bo = (const float*)d_in[11];

    __nv_bfloat16 *pqh, *pql, *pkh, *pkl, *pvh, *pvl, *pah, *pal, *pwh, *pwl;
    unsigned char* pm8;
    cudaGetSymbolAddress((void**)&pqh, g_qhi);
    cudaGetSymbolAddress((void**)&pql, g_qlo);
    cudaGetSymbolAddress((void**)&pkh, g_khi);
    cudaGetSymbolAddress((void**)&pkl, g_klo);
    cudaGetSymbolAddress((void**)&pvh, g_vhi);
    cudaGetSymbolAddress((void**)&pvl, g_vlo);
    cudaGetSymbolAddress((void**)&pah, g_ahi);
    cudaGetSymbolAddress((void**)&pal, g_alo);
    cudaGetSymbolAddress((void**)&pwh, g_whi);
    cudaGetSymbolAddress((void**)&pwl, g_wlo);
    cudaGetSymbolAddress((void**)&pm8, g_m8);

    cudaFuncSetAttribute(gemm_tc,
                         cudaFuncAttributeMaxDynamicSharedMemorySize, G_SMEM);
    cudaFuncSetAttribute(attn_tc,
                         cudaFuncAttributeMaxDynamicSharedMemorySize, ATT_SMEM);

    conv_mask<<<16384, 256>>>((const int4*)mask, (uchar4*)pm8, 4194304);

    #define PROJ0(Asrc, Wsrc, Bsrc, OH, OL)                                   \
        conv_split<<<8192, 256>>>((const float4*)(Asrc), (uint2*)pah,         \
                                  (uint2*)pal, 2097152);                      \
        conv_split<<<1024, 256>>>((const float4*)(Wsrc), (uint2*)pwh,         \
                                  (uint2*)pwl, 262144);                       \
        gemm_tc<<<dim3(8, 64), 256, G_SMEM>>>(pah, pal, pwh, pwl, (Bsrc),     \
                                              nullptr, (OH), (OL), 0);

    PROJ0(query, wq, bq, pqh, pql)
    PROJ0(key_,  wk, bk, pkh, pkl)
    PROJ0(value, wv, bv, pvh, pvl)
    #undef PROJ0

    attn_tc<<<dim3(16, 64), 256, ATT_SMEM>>>(pqh, pql, pkh, pkl, pvh, pvl,
                                             pm8, pah, pal);

    conv_split<<<1024, 256>>>((const float4*)wo, (uint2*)pwh, (uint2*)pwl,
                              262144);
    gemm_tc<<<dim3(8, 64), 256, G_SMEM>>>(pah, pal, pwh, pwl, bo,
                                          (float*)d_out, nullptr, nullptr, 1);
}

// round 6
// speedup vs baseline: 3.0872x; 1.5083x over previous
#include <cuda_runtime.h>
#include <cuda_fp16.h>
#include <cstdint>

#define EPS_VAL 1e-11f

// ---------------- scratch (__device__ globals; no allocs allowed) -----------
__device__ __half g_aq[8192*1024];             // fp16 A inputs (single)
__device__ __half g_ak[8192*1024];
__device__ __half g_av[8192*1024];
__device__ __half g_ao1[8192*1024];            // attention out (single fp16)
__device__ __half g_wqh[1024*1024], g_wql[1024*1024];
__device__ __half g_wkh[1024*1024], g_wkl[1024*1024];
__device__ __half g_wvh[1024*1024], g_wvl[1024*1024];
__device__ __half g_woh[1024*1024], g_wol[1024*1024];
__device__ __half g_qhi[4*16*2048*64];         // Q split [B,H,S,dk]
__device__ __half g_qlo[4*16*2048*64];
__device__ __half g_k1 [4*16*2048*64];         // K single
__device__ __half g_vhi[4*16*2048*64];         // V split
__device__ __half g_vlo[4*16*2048*64];
__device__ unsigned char g_m8[4*2048*2048];    // int8 mask

// ---------------- PTX helpers (generic ISA, valid at compute_103) -----------
__device__ __forceinline__ uint32_t smem_u32(const void* p) {
    uint32_t a;
    asm("{ .reg .u64 t; cvta.to.shared.u64 t, %1; cvt.u32.u64 %0, t; }"
        : "=r"(a) : "l"(p));
    return a;
}
__device__ __forceinline__ void cpa16(uint32_t dst, const void* src) {
    asm volatile("cp.async.cg.shared.global [%0], [%1], 16;"
                 :: "r"(dst), "l"(src) : "memory");
}
#define CP_COMMIT() asm volatile("cp.async.commit_group;" ::: "memory")
#define CP_WAIT(n)  asm volatile("cp.async.wait_group %0;" :: "n"(n) : "memory")

#define LDSM4(r0, r1, r2, r3, addr)                                          \
    asm volatile("ldmatrix.sync.aligned.m8n8.x4.shared.b16 {%0,%1,%2,%3}, [%4];" \
                 : "=r"(r0), "=r"(r1), "=r"(r2), "=r"(r3) : "r"(addr))
#define LDSM4T(r0, r1, r2, r3, addr)                                         \
    asm volatile("ldmatrix.sync.aligned.m8n8.x4.trans.shared.b16 {%0,%1,%2,%3}, [%4];" \
                 : "=r"(r0), "=r"(r1), "=r"(r2), "=r"(r3) : "r"(addr))

#define MMA16816(d, a, b)                                                    \
    asm volatile("mma.sync.aligned.m16n8k16.row.col.f32.f16.f16.f32 "        \
                 "{%0,%1,%2,%3}, {%4,%5,%6,%7}, {%8,%9}, {%0,%1,%2,%3};"     \
                 : "+f"((d)[0]), "+f"((d)[1]), "+f"((d)[2]), "+f"((d)[3])    \
                 : "r"((a)[0]), "r"((a)[1]), "r"((a)[2]), "r"((a)[3]),       \
                   "r"((b)[0]), "r"((b)[1]))

__device__ __forceinline__ uint32_t pack_h2(float a, float b) {
    __half2 h = __floats2half2_rn(a, b);
    return *reinterpret_cast<uint32_t*>(&h);
}

// ---------------- conversions ------------------------------------------------
__global__ __launch_bounds__(256) void conv_h1(
    const float4* __restrict__ src, uint2* __restrict__ dst, int n4)
{
    int i = blockIdx.x * blockDim.x + threadIdx.x;
    if (i >= n4) return;
    float4 v = src[i];
    dst[i] = make_uint2(pack_h2(v.x, v.y), pack_h2(v.z, v.w));
}

__global__ __launch_bounds__(256) void conv_hsplit(
    const float4* __restrict__ src, uint2* __restrict__ hi,
    uint2* __restrict__ lo, int n4)
{
    int i = blockIdx.x * blockDim.x + threadIdx.x;
    if (i >= n4) return;
    float4 v = src[i];
    __half h0 = __float2half_rn(v.x), h1 = __float2half_rn(v.y);
    __half h2 = __float2half_rn(v.z), h3 = __float2half_rn(v.w);
    hi[i] = make_uint2(pack_h2(v.x, v.y), pack_h2(v.z, v.w));
    lo[i] = make_uint2(
        pack_h2(v.x - __half2float(h0), v.y - __half2float(h1)),
        pack_h2(v.z - __half2float(h2), v.w - __half2float(h3)));
}

__global__ __launch_bounds__(256) void conv_mask(
    const int4* __restrict__ src, uchar4* __restrict__ dst, int n4)
{
    int i = blockIdx.x * blockDim.x + threadIdx.x;
    if (i >= n4) return;
    int4 v = src[i];
    dst[i] = make_uchar4((unsigned char)v.x, (unsigned char)v.y,
                         (unsigned char)v.z, (unsigned char)v.w);
}

// ---------------- fp16 2-term GEMM core (mma.sync) --------------------------
// C = A(fp16) @ (Wh+Wl)^T, fp32 accum. CTA 128x128, BK=64, 3-stage cp.async,
// one sync/iter, prefetch-first, double-buffered ldmatrix fragments.
#define G_MAT 16384
#define G_STAGE (3 * G_MAT)                  // A, Wh, Wl
#define G_SMEM (3 * G_STAGE)                 // 147456

__device__ __forceinline__ void g_stage3(
    uint32_t sb, const __half* __restrict__ pA, const __half* __restrict__ pWh,
    const __half* __restrict__ pWl, int kt, int tid)
{
    const __half* srcs[3] = {pA, pWh, pWl};
    #pragma unroll
    for (int m = 0; m < 3; ++m) {
        uint32_t mb = sb + m * G_MAT;
        const __half* sp = srcs[m];
        #pragma unroll
        for (int i = 0; i < 4; ++i) {
            int seg = tid + (i << 8);
            int row = seg >> 3, cs = seg & 7;
            cpa16(mb + row * 128 + ((cs << 4) ^ ((row & 7) << 4)),
                  sp + (size_t)row * 1024 + (kt << 6) + (cs << 3));
        }
    }
    CP_COMMIT();
}

#define GLOAD_FRAGS(buf, kk, sb)                                             \
    do {                                                                     \
        const int x_ = ((kk) << 5) + lxh;                                    \
        _Pragma("unroll")                                                    \
        for (int mi = 0; mi < 4; ++mi) {                                     \
            int row = wm + (mi << 4) + lr;                                   \
            uint32_t ad = (sb) + row * 128 + (x_ ^ ((row & 7) << 4));        \
            LDSM4(af[buf][mi][0], af[buf][mi][1], af[buf][mi][2],            \
                  af[buf][mi][3], ad);                                       \
        }                                                                    \
        _Pragma("unroll")                                                    \
        for (int g = 0; g < 2; ++g) {                                        \
            int row = wn + (g << 4) + lr;                                    \
            uint32_t wd = (sb) + G_MAT + row * 128 + (x_ ^ ((row & 7) << 4));\
            uint32_t r0, r1, r2, r3;                                         \
            LDSM4(r0, r1, r2, r3, wd);                                       \
            whf[buf][2*g][0] = r0; whf[buf][2*g][1] = r2;                    \
            whf[buf][2*g+1][0] = r1; whf[buf][2*g+1][1] = r3;                \
            LDSM4(r0, r1, r2, r3, wd + G_MAT);                               \
            wlf[buf][2*g][0] = r0; wlf[buf][2*g][1] = r2;                    \
            wlf[buf][2*g+1][0] = r1; wlf[buf][2*g+1][1] = r3;                \
        }                                                                    \
    } while (0)

#define GEMM_BODY(pA, pWh, pWl)                                              \
    g_stage3(sb0,           (pA), (pWh), (pWl), 0, tid);                     \
    g_stage3(sb0 + G_STAGE, (pA), (pWh), (pWl), 1, tid);                     \
    uint32_t af[2][4][4], whf[2][4][2], wlf[2][4][2];                        \
    for (int j = 0; j < 16; ++j) {                                           \
        if (j < 15) { CP_WAIT(1); } else { CP_WAIT(0); }                     \
        __syncthreads();                                                     \
        if (j + 2 < 16)                                                      \
            g_stage3(sb0 + ((j + 2) % 3) * G_STAGE, (pA), (pWh), (pWl),      \
                     j + 2, tid);                                            \
        const uint32_t sb = sb0 + (j % 3) * G_STAGE;                         \
        GLOAD_FRAGS(0, 0, sb);                                               \
        _Pragma("unroll")                                                    \
        for (int kk = 0; kk < 4; ++kk) {                                     \
            if (kk < 3) GLOAD_FRAGS((kk + 1) & 1, kk + 1, sb);               \
            const int cb = kk & 1;                                           \
            _Pragma("unroll")                                                \
            for (int mi = 0; mi < 4; ++mi)                                   \
                _Pragma("unroll")                                            \
                for (int ni = 0; ni < 4; ++ni) {                             \
                    MMA16816(acc[mi][ni], af[cb][mi], whf[cb][ni]);          \
                    MMA16816(acc[mi][ni], af[cb][mi], wlf[cb][ni]);          \
                }                                                            \
        }                                                                    \
    }

__global__ __launch_bounds__(256, 1) void gemm_qkv(
    const float* __restrict__ bq, const float* __restrict__ bk,
    const float* __restrict__ bv)
{
    extern __shared__ __align__(128) char dynsm[];
    __shared__ float bias_s[128];

    const int tid  = threadIdx.x;
    const int wid  = tid >> 5;
    const int lane = tid & 31;
    const int m0 = blockIdx.y << 7;
    const int n0 = blockIdx.x << 7;
    const int z  = blockIdx.z;
    const int wm = (wid >> 2) << 6;
    const int wn = (wid & 3) << 5;
    const int lr = lane & 15;
    const int lxh = (lane >> 4) << 4;

    const __half* A  = (z == 0) ? g_aq  : (z == 1) ? g_ak  : g_av;
    const __half* Wh = (z == 0) ? g_wqh : (z == 1) ? g_wkh : g_wvh;
    const __half* Wl = (z == 0) ? g_wql : (z == 1) ? g_wkl : g_wvl;
    const float* bias = (z == 0) ? bq : (z == 1) ? bk : bv;

    if (tid < 128) bias_s[tid] = bias[n0 + tid];

    const uint32_t sb0 = smem_u32(dynsm);
    const __half* pA  = A  + (size_t)m0 * 1024;
    const __half* pWh = Wh + (size_t)n0 * 1024;
    const __half* pWl = Wl + (size_t)n0 * 1024;

    float acc[4][4][4] = {};
    GEMM_BODY(pA, pWh, pWl)

    // epilogue: scatter [B,H,S,dk]; z=0 Q split, z=1 K single, z=2 V split
    const int rbase = m0 + wm + (lane >> 2);
    const int cbase = n0 + wn + ((lane & 3) << 1);
    #pragma unroll
    for (int mi = 0; mi < 4; ++mi) {
        #pragma unroll
        for (int ni = 0; ni < 4; ++ni) {
            int col = cbase + (ni << 3);
            float b0 = bias_s[col - n0], b1 = bias_s[col - n0 + 1];
            #pragma unroll
            for (int half = 0; half < 2; ++half) {
                int row = rbase + (mi << 4) + (half << 3);
                float v0 = acc[mi][ni][half*2]   + b0;
                float v1 = acc[mi][ni][half*2+1] + b1;
                int h = col >> 6, d = col & 63;
                int bb = row >> 11, s = row & 2047;
                size_t idx = ((size_t)((bb << 4) + h) * 2048 + s) * 64 + d;
                if (z == 1) {
                    *reinterpret_cast<uint32_t*>(&g_k1[idx]) = pack_h2(v0, v1);
                } else {
                    __half h0 = __float2half_rn(v0), h1 = __float2half_rn(v1);
                    uint32_t hi = *reinterpret_cast<uint32_t*>(&h0) |
                                  ((uint32_t)*reinterpret_cast<uint16_t*>(&h1) << 16);
                    uint32_t lo = pack_h2(v0 - __half2float(h0),
                                          v1 - __half2float(h1));
                    if (z == 0) {
                        *reinterpret_cast<uint32_t*>(&g_qhi[idx]) = hi;
                        *reinterpret_cast<uint32_t*>(&g_qlo[idx]) = lo;
                    } else {
                        *reinterpret_cast<uint32_t*>(&g_vhi[idx]) = hi;
                        *reinterpret_cast<uint32_t*>(&g_vlo[idx]) = lo;
                    }
                }
            }
        }
    }
}

__global__ __launch_bounds__(256, 1) void gemm_out(
    const float* __restrict__ bo, float* __restrict__ outf)
{
    extern __shared__ __align__(128) char dynsm[];
    __shared__ float bias_s[128];

    const int tid  = threadIdx.x;
    const int wid  = tid >> 5;
    const int lane = tid & 31;
    const int m0 = blockIdx.y << 7;
    const int n0 = blockIdx.x << 7;
    const int wm = (wid >> 2) << 6;
    const int wn = (wid & 3) << 5;
    const int lr = lane & 15;
    const int lxh = (lane >> 4) << 4;

    if (tid < 128) bias_s[tid] = bo[n0 + tid];

    const uint32_t sb0 = smem_u32(dynsm);
    const __half* pA  = g_ao1 + (size_t)m0 * 1024;
    const __half* pWh = g_woh + (size_t)n0 * 1024;
    const __half* pWl = g_wol + (size_t)n0 * 1024;

    float acc[4][4][4] = {};
    GEMM_BODY(pA, pWh, pWl)

    const int rbase = m0 + wm + (lane >> 2);
    const int cbase = n0 + wn + ((lane & 3) << 1);
    #pragma unroll
    for (int mi = 0; mi < 4; ++mi)
        #pragma unroll
        for (int ni = 0; ni < 4; ++ni) {
            int col = cbase + (ni << 3);
            float b0 = bias_s[col - n0], b1 = bias_s[col - n0 + 1];
            #pragma unroll
            for (int half = 0; half < 2; ++half) {
                int row = rbase + (mi << 4) + (half << 3);
                *reinterpret_cast<float2*>(&outf[(size_t)row * 1024 + col]) =
                    make_float2(acc[mi][ni][half*2] + b0,
                                acc[mi][ni][half*2+1] + b1);
            }
        }
}

// ---------------- tensor-core flash attention (fp16 2-term) -----------------
// Q split hi/lo (persistent frags) x K single; P single x V split hi/lo.
#define ATT_KV 16384
#define ATT_M_PITCH 144
#define ATT_M_BYTES (128 * ATT_M_PITCH)
#define ATT_STAGE (3*ATT_KV + ATT_M_BYTES)       // K, Vh, Vl, mask = 67584
#define ATT_SMEM (2*ATT_KV + 2*ATT_STAGE)        // 167936

__device__ __forceinline__ void att_stage(
    uint32_t sb, const __half* __restrict__ K, const __half* __restrict__ Vh,
    const __half* __restrict__ Vl, const unsigned char* __restrict__ M,
    int k0, int q0, int tid)
{
    #pragma unroll
    for (int i = 0; i < 4; ++i) {
        int seg = tid + (i << 8);
        int row = seg >> 3, cs = seg & 7;
        uint32_t so = row * 128 + ((cs << 4) ^ ((row & 7) << 4));
        size_t gofs = (size_t)(k0 + row) * 64 + (cs << 3);
        cpa16(sb + so,            K  + gofs);
        cpa16(sb + ATT_KV + so,   Vh + gofs);
        cpa16(sb + 2*ATT_KV + so, Vl + gofs);
        cpa16(sb + 3*ATT_KV + row * ATT_M_PITCH + (cs << 4),
              M + (size_t)(q0 + row) * 2048 + k0 + (cs << 4));
    }
    CP_COMMIT();
}

__global__ __launch_bounds__(256, 1) void attn_tc()
{
    extern __shared__ __align__(128) char sm[];
    const int tid  = threadIdx.x;
    const int wid  = tid >> 5;
    const int lane = tid & 31;
    const int bh = blockIdx.y;
    const int b = bh >> 4, h = bh & 15;
    const int q0 = blockIdx.x << 7;

    const uint32_t smb = smem_u32(sm);
    const uint32_t stg[2] = {smb + 2*ATT_KV, smb + 2*ATT_KV + ATT_STAGE};

    const size_t hofs = (size_t)bh * 2048 * 64;
    const __half* gqh = g_qhi + hofs + (size_t)q0 * 64;
    const __half* gql = g_qlo + hofs + (size_t)q0 * 64;
    const __half* gk  = g_k1 + hofs;
    const __half* gvh = g_vhi + hofs;
    const __half* gvl = g_vlo + hofs;
    const unsigned char* gm = g_m8 + (size_t)b * 2048 * 2048;

    #pragma unroll
    for (int i = 0; i < 4; ++i) {
        int seg = tid + (i << 8);
        int row = seg >> 3, cs = seg & 7;
        uint32_t so = row * 128 + ((cs << 4) ^ ((row & 7) << 4));
        size_t gofs = (size_t)row * 64 + (cs << 3);
        cpa16(smb + so,          gqh + gofs);
        cpa16(smb + ATT_KV + so, gql + gofs);
    }
    CP_COMMIT();
    att_stage(stg[0], gk, gvh, gvl, gm, 0,   q0, tid);
    att_stage(stg[1], gk, gvh, gvl, gm, 128, q0, tid);

    CP_WAIT(2);
    __syncthreads();

    const int lr  = lane & 15;
    const int lxh = (lane >> 4) << 4;
    const int r   = lane >> 2;
    const int c2  = (lane & 3) << 1;

    uint32_t qh[4][4], ql[4][4];
    {
        int row = (wid << 4) + lr;
        uint32_t rb = smb + row * 128;
        uint32_t sw = (row & 7) << 4;
        #pragma unroll
        for (int kk = 0; kk < 4; ++kk) {
            uint32_t ad = rb + (((kk << 5) + lxh) ^ sw);
            LDSM4(qh[kk][0], qh[kk][1], qh[kk][2], qh[kk][3], ad);
            LDSM4(ql[kk][0], ql[kk][1], ql[kk][2], ql[kk][3], ad + ATT_KV);
        }
    }

    float o[8][4] = {};
    float m0 = -1e30f, m1 = -1e30f, l0 = 0.f, l1 = 0.f;
    const int qr0 = (wid << 4) + r;
    const char* msm_rel[2] = {sm + 2*ATT_KV + 3*ATT_KV,
                              sm + 2*ATT_KV + ATT_STAGE + 3*ATT_KV};

    for (int kt = 0; kt < 16; ++kt) {
        if (kt < 15) { CP_WAIT(1); } else { CP_WAIT(0); }
        __syncthreads();
        const uint32_t sb = stg[kt & 1];
        const char* msk = msm_rel[kt & 1];

        // ---- S = Q K^T : (Qh + Ql) x K ----
        float sc[16][4];
        #pragma unroll
        for (int nt = 0; nt < 16; ++nt)
            #pragma unroll
            for (int j = 0; j < 4; ++j) sc[nt][j] = 0.f;

        #pragma unroll
        for (int g = 0; g < 8; ++g) {
            int krow = (g << 4) + lr;
            uint32_t rb = sb + krow * 128;
            uint32_t sw = (krow & 7) << 4;
            #pragma unroll
            for (int kk = 0; kk < 4; ++kk) {
                uint32_t ad = rb + (((kk << 5) + lxh) ^ sw);
                uint32_t k0r, k1r, k2r, k3r;
                LDSM4(k0r, k1r, k2r, k3r, ad);
                uint32_t bE[2] = {k0r, k2r}, bO[2] = {k1r, k3r};
                MMA16816(sc[2*g],   qh[kk], bE);
                MMA16816(sc[2*g],   ql[kk], bE);
                MMA16816(sc[2*g+1], qh[kk], bO);
                MMA16816(sc[2*g+1], ql[kk], bO);
            }
        }

        // ---- scale + mask + online softmax ----
        float mx0 = -1e30f, mx1 = -1e30f;
        #pragma unroll
        for (int nt = 0; nt < 16; ++nt) {
            const unsigned char* mr0 = (const unsigned char*)
                (msk + qr0 * ATT_M_PITCH + (nt << 3) + c2);
            const unsigned char* mr1 = mr0 + 8 * ATT_M_PITCH;
            float v;
            v = mr0[0] ? sc[nt][0] * 0.125f : EPS_VAL; sc[nt][0] = v; mx0 = fmaxf(mx0, v);
            v = mr0[1] ? sc[nt][1] * 0.125f : EPS_VAL; sc[nt][1] = v; mx0 = fmaxf(mx0, v);
            v = mr1[0] ? sc[nt][2] * 0.125f : EPS_VAL; sc[nt][2] = v; mx1 = fmaxf(mx1, v);
            v = mr1[1] ? sc[nt][3] * 0.125f : EPS_VAL; sc[nt][3] = v; mx1 = fmaxf(mx1, v);
        }
        mx0 = fmaxf(mx0, __shfl_xor_sync(~0u, mx0, 1));
        mx0 = fmaxf(mx0, __shfl_xor_sync(~0u, mx0, 2));
        mx1 = fmaxf(mx1, __shfl_xor_sync(~0u, mx1, 1));
        mx1 = fmaxf(mx1, __shfl_xor_sync(~0u, mx1, 2));
        float mn0 = fmaxf(m0, mx0), mn1 = fmaxf(m1, mx1);
        float co0 = __expf(m0 - mn0), co1 = __expf(m1 - mn1);
        m0 = mn0; m1 = mn1;

        float rs0 = 0.f, rs1 = 0.f;
        #pragma unroll
        for (int nt = 0; nt < 16; ++nt) {
            float e;
            e = __expf(sc[nt][0] - mn0); sc[nt][0] = e; rs0 += e;
            e = __expf(sc[nt][1] - mn0); sc[nt][1] = e; rs0 += e;
            e = __expf(sc[nt][2] - mn1); sc[nt][2] = e; rs1 += e;
            e = __expf(sc[nt][3] - mn1); sc[nt][3] = e; rs1 += e;
        }
        rs0 += __shfl_xor_sync(~0u, rs0, 1); rs0 += __shfl_xor_sync(~0u, rs0, 2);
        rs1 += __shfl_xor_sync(~0u, rs1, 1); rs1 += __shfl_xor_sync(~0u, rs1, 2);
        l0 = l0 * co0 + rs0;
        l1 = l1 * co1 + rs1;
        #pragma unroll
        for (int ni = 0; ni < 8; ++ni) {
            o[ni][0] *= co0; o[ni][1] *= co0;
            o[ni][2] *= co1; o[ni][3] *= co1;
        }

        // ---- O += P x (Vh + Vl), P single fp16 ----
        #pragma unroll
        for (int t = 0; t < 8; ++t) {
            uint32_t aP[4];
            #pragma unroll
            for (int u = 0; u < 4; ++u)
                aP[u] = pack_h2(sc[2*t + (u >> 1)][(u & 1) * 2],
                                sc[2*t + (u >> 1)][(u & 1) * 2 + 1]);
            int vrow = (t << 4) + lr;
            uint32_t rb = sb + ATT_KV + vrow * 128;
            uint32_t sw = (vrow & 7) << 4;
            #pragma unroll
            for (int dp = 0; dp < 4; ++dp) {
                uint32_t ad = rb + (((dp << 5) + lxh) ^ sw);
                uint32_t h0, h1, h2, h3, L0, L1, L2, L3;
                LDSM4T(h0, h1, h2, h3, ad);
                LDSM4T(L0, L1, L2, L3, ad + ATT_KV);
                uint32_t bh0[2] = {h0, h1}, bh1[2] = {h2, h3};
                uint32_t bl0[2] = {L0, L1}, bl1[2] = {L2, L3};
                MMA16816(o[2*dp],   aP, bh0);
                MMA16816(o[2*dp],   aP, bl0);
                MMA16816(o[2*dp+1], aP, bh1);
                MMA16816(o[2*dp+1], aP, bl1);
            }
        }

        __syncthreads();
        if (kt + 2 < 16)
            att_stage(stg[kt & 1], gk, gvh, gvl, gm, (kt + 2) << 7, q0, tid);
    }

    // ---- epilogue: normalize, single fp16 store [B,S,1024] ----
    float i0 = 1.f / l0, i1 = 1.f / l1;
    int row0 = q0 + (wid << 4) + r;
    size_t base0 = ((size_t)(b * 2048) + row0) * 1024 + h * 64;
    size_t base1 = base0 + 8 * 1024;
    #pragma unroll
    for (int ni = 0; ni < 8; ++ni) {
        int d = (ni << 3) + c2;
        *reinterpret_cast<uint32_t*>(&g_ao1[base0 + d]) =
            pack_h2(o[ni][0] * i0, o[ni][1] * i0);
        *reinterpret_cast<uint32_t*>(&g_ao1[base1 + d]) =
            pack_h2(o[ni][2] * i1, o[ni][3] * i1);
    }
}

// ---------------------------------------------------------------------------
extern "C" void kernel_launch(void* const* d_in, const int* in_sizes, int n_in,
                              void* d_out, int out_size)
{
    const float* query = (const float*)d_in[0];
    const float* key_  = (const float*)d_in[1];
    const float* value = (const float*)d_in[2];
    const int*   mask  = (const int*)  d_in[3];
    const float* wq = (const float*)d_in[4];
    const float* bq = (const float*)d_in[5];
    const float* wk = (const float*)d_in[6];
    const float* bk = (const float*)d_in[7];
    const float* wv = (const float*)d_in[8];
    const float* bv = (const float*)d_in[9];
    const float* wo = (const float*)d_in[10];
    const float* bo = (const float*)d_in[11];

    void *paq, *pak, *pav, *pwqh, *pwql, *pwkh, *pwkl, *pwvh, *pwvl,
         *pwoh, *pwol, *pm8;
    cudaGetSymbolAddress(&paq,  g_aq);
    cudaGetSymbolAddress(&pak,  g_ak);
    cudaGetSymbolAddress(&pav,  g_av);
    cudaGetSymbolAddress(&pwqh, g_wqh);
    cudaGetSymbolAddress(&pwql, g_wql);
    cudaGetSymbolAddress(&pwkh, g_wkh);
    cudaGetSymbolAddress(&pwkl, g_wkl);
    cudaGetSymbolAddress(&pwvh, g_wvh);
    cudaGetSymbolAddress(&pwvl, g_wvl);
    cudaGetSymbolAddress(&pwoh, g_woh);
    cudaGetSymbolAddress(&pwol, g_wol);
    cudaGetSymbolAddress(&pm8,  g_m8);

    cudaFuncSetAttribute(gemm_qkv,
                         cudaFuncAttributeMaxDynamicSharedMemorySize, G_SMEM);
    cudaFuncSetAttribute(gemm_out,
                         cudaFuncAttributeMaxDynamicSharedMemorySize, G_SMEM);
    cudaFuncSetAttribute(attn_tc,
                         cudaFuncAttributeMaxDynamicSharedMemorySize, ATT_SMEM);

    conv_mask<<<16384, 256>>>((const int4*)mask, (uchar4*)pm8, 4194304);
    conv_h1<<<8192, 256>>>((const float4*)query, (uint2*)paq, 2097152);
    conv_h1<<<8192, 256>>>((const float4*)key_,  (uint2*)pak, 2097152);
    conv_h1<<<8192, 256>>>((const float4*)value, (uint2*)pav, 2097152);
    conv_hsplit<<<1024, 256>>>((const float4*)wq, (uint2*)pwqh, (uint2*)pwql, 262144);
    conv_hsplit<<<1024, 256>>>((const float4*)wk, (uint2*)pwkh, (uint2*)pwkl, 262144);
    conv_hsplit<<<1024, 256>>>((const float4*)wv, (uint2*)pwvh, (uint2*)pwvl, 262144);
    conv_hsplit<<<1024, 256>>>((const float4*)wo, (uint2*)pwoh, (uint2*)pwol, 262144);

    gemm_qkv<<<dim3(8, 64, 3), 256, G_SMEM>>>(bq, bk, bv);
    attn_tc<<<dim3(16, 64), 256, ATT_SMEM>>>();
    gemm_out<<<dim3(8, 64), 256, G_SMEM>>>(bo, (float*)d_out);
}

// round 7
// speedup vs baseline: 3.4772x; 1.1263x over previous
#include <cuda_runtime.h>
#include <cuda_fp16.h>
#include <cstdint>

#define EPS_VAL 1e-11f

// ---------------- scratch (__device__ globals; no allocs allowed) -----------
__device__ __half g_aq[8192*1024];             // fp16 A inputs (single)
__device__ __half g_ak[8192*1024];
__device__ __half g_av[8192*1024];
__device__ __half g_ao1[8192*1024];            // attention out (single fp16)
__device__ __half g_wqh[1024*1024], g_wql[1024*1024];
__device__ __half g_wkh[1024*1024], g_wkl[1024*1024];
__device__ __half g_wvh[1024*1024], g_wvl[1024*1024];
__device__ __half g_woh[1024*1024], g_wol[1024*1024];
__device__ __half g_qhi[4*16*2048*64];         // Q split (pre-scaled by 1/8)
__device__ __half g_qlo[4*16*2048*64];
__device__ __half g_k1 [4*16*2048*64];         // K single
__device__ __half g_vhi[4*16*2048*64];         // V split
__device__ __half g_vlo[4*16*2048*64];
__device__ uint32_t g_mbits[4*2048*64];        // bit mask: 64 words per row

// ---------------- PTX helpers (generic ISA, valid at compute_103) -----------
__device__ __forceinline__ uint32_t smem_u32(const void* p) {
    uint32_t a;
    asm("{ .reg .u64 t; cvta.to.shared.u64 t, %1; cvt.u32.u64 %0, t; }"
        : "=r"(a) : "l"(p));
    return a;
}
__device__ __forceinline__ void cpa16(uint32_t dst, const void* src) {
    asm volatile("cp.async.cg.shared.global [%0], [%1], 16;"
                 :: "r"(dst), "l"(src) : "memory");
}
#define CP_COMMIT() asm volatile("cp.async.commit_group;" ::: "memory")
#define CP_WAIT(n)  asm volatile("cp.async.wait_group %0;" :: "n"(n) : "memory")

#define LDSM4(r0, r1, r2, r3, addr)                                          \
    asm volatile("ldmatrix.sync.aligned.m8n8.x4.shared.b16 {%0,%1,%2,%3}, [%4];" \
                 : "=r"(r0), "=r"(r1), "=r"(r2), "=r"(r3) : "r"(addr))
#define LDSM4T(r0, r1, r2, r3, addr)                                         \
    asm volatile("ldmatrix.sync.aligned.m8n8.x4.trans.shared.b16 {%0,%1,%2,%3}, [%4];" \
                 : "=r"(r0), "=r"(r1), "=r"(r2), "=r"(r3) : "r"(addr))

#define MMA16816(d, a, b)                                                    \
    asm volatile("mma.sync.aligned.m16n8k16.row.col.f32.f16.f16.f32 "        \
                 "{%0,%1,%2,%3}, {%4,%5,%6,%7}, {%8,%9}, {%0,%1,%2,%3};"     \
                 : "+f"((d)[0]), "+f"((d)[1]), "+f"((d)[2]), "+f"((d)[3])    \
                 : "r"((a)[0]), "r"((a)[1]), "r"((a)[2]), "r"((a)[3]),       \
                   "r"((b)[0]), "r"((b)[1]))

__device__ __forceinline__ uint32_t pack_h2(float a, float b) {
    __half2 h = __floats2half2_rn(a, b);
    return *reinterpret_cast<uint32_t*>(&h);
}

// ---------------- conversions ------------------------------------------------
__global__ __launch_bounds__(256) void conv_h1(
    const float4* __restrict__ src, uint2* __restrict__ dst, int n4)
{
    int i = blockIdx.x * blockDim.x + threadIdx.x;
    if (i >= n4) return;
    float4 v = src[i];
    dst[i] = make_uint2(pack_h2(v.x, v.y), pack_h2(v.z, v.w));
}

__global__ __launch_bounds__(256) void conv_hsplit(
    const float4* __restrict__ src, uint2* __restrict__ hi,
    uint2* __restrict__ lo, int n4)
{
    int i = blockIdx.x * blockDim.x + threadIdx.x;
    if (i >= n4) return;
    float4 v = src[i];
    __half h0 = __float2half_rn(v.x), h1 = __float2half_rn(v.y);
    __half h2 = __float2half_rn(v.z), h3 = __float2half_rn(v.w);
    hi[i] = make_uint2(pack_h2(v.x, v.y), pack_h2(v.z, v.w));
    lo[i] = make_uint2(
        pack_h2(v.x - __half2float(h0), v.y - __half2float(h1)),
        pack_h2(v.z - __half2float(h2), v.w - __half2float(h3)));
}

__global__ __launch_bounds__(256) void conv_maskbits(
    const int* __restrict__ src, uint32_t* __restrict__ dst)
{
    int gw = (blockIdx.x * blockDim.x + threadIdx.x) >> 5;
    int lane = threadIdx.x & 31;
    int v = src[(size_t)gw * 32 + lane];
    uint32_t b = __ballot_sync(0xffffffffu, v != 0);
    if (lane == 0) dst[gw] = b;
}

// ---------------- fp16 2-term GEMM core (mma.sync) --------------------------
// C = A(fp16) @ (Wh+Wl)^T. CTA 128x128, BK=64, 2-stage cp.async, 2 CTAs/SM.
#define G_MAT 16384
#define G_STAGE (3 * G_MAT)                  // A, Wh, Wl = 49152
#define G_SMEM (2 * G_STAGE)                 // 98304

__device__ __forceinline__ void g_stage3(
    uint32_t sb, const __half* __restrict__ pA, const __half* __restrict__ pWh,
    const __half* __restrict__ pWl, int kt, int tid)
{
    const __half* srcs[3] = {pA, pWh, pWl};
    #pragma unroll
    for (int m = 0; m < 3; ++m) {
        uint32_t mb = sb + m * G_MAT;
        const __half* sp = srcs[m];
        #pragma unroll
        for (int i = 0; i < 4; ++i) {
            int seg = tid + (i << 8);
            int row = seg >> 3, cs = seg & 7;
            cpa16(mb + row * 128 + ((cs << 4) ^ ((row & 7) << 4)),
                  sp + (size_t)row * 1024 + (kt << 6) + (cs << 3));
        }
    }
    CP_COMMIT();
}

#define GLOAD_FRAGS(kk, sb)                                                  \
    do {                                                                     \
        const int x_ = ((kk) << 5) + lxh;                                    \
        _Pragma("unroll")                                                    \
        for (int mi = 0; mi < 4; ++mi) {                                     \
            int row = wm + (mi << 4) + lr;                                   \
            uint32_t ad = (sb) + row * 128 + (x_ ^ ((row & 7) << 4));        \
            LDSM4(af[mi][0], af[mi][1], af[mi][2], af[mi][3], ad);           \
        }                                                                    \
        _Pragma("unroll")                                                    \
        for (int g = 0; g < 2; ++g) {                                        \
            int row = wn + (g << 4) + lr;                                    \
            uint32_t wd = (sb) + G_MAT + row * 128 + (x_ ^ ((row & 7) << 4));\
            uint32_t r0, r1, r2, r3;                                         \
            LDSM4(r0, r1, r2, r3, wd);                                       \
            whf[2*g][0] = r0; whf[2*g][1] = r2;                              \
            whf[2*g+1][0] = r1; whf[2*g+1][1] = r3;                          \
            LDSM4(r0, r1, r2, r3, wd + G_MAT);                               \
            wlf[2*g][0] = r0; wlf[2*g][1] = r2;                              \
            wlf[2*g+1][0] = r1; wlf[2*g+1][1] = r3;                          \
        }                                                                    \
    } while (0)

#define GEMM_BODY(pA, pWh, pWl)                                              \
    g_stage3(sb0, (pA), (pWh), (pWl), 0, tid);                               \
    uint32_t af[4][4], whf[4][2], wlf[4][2];                                 \
    for (int j = 0; j < 16; ++j) {                                           \
        CP_WAIT(0);                                                          \
        __syncthreads();                                                     \
        if (j + 1 < 16)                                                      \
            g_stage3(sb0 + ((j + 1) & 1) * G_STAGE, (pA), (pWh), (pWl),      \
                     j + 1, tid);                                            \
        const uint32_t sb = sb0 + (j & 1) * G_STAGE;                         \
        _Pragma("unroll")                                                    \
        for (int kk = 0; kk < 4; ++kk) {                                     \
            GLOAD_FRAGS(kk, sb);                                             \
            _Pragma("unroll")                                                \
            for (int mi = 0; mi < 4; ++mi)                                   \
                _Pragma("unroll")                                            \
                for (int ni = 0; ni < 4; ++ni) {                             \
                    MMA16816(acc[mi][ni], af[mi], whf[ni]);                  \
                    MMA16816(acc[mi][ni], af[mi], wlf[ni]);                  \
                }                                                            \
        }                                                                    \
    }

__global__ __launch_bounds__(256, 2) void gemm_qkv(
    const float* __restrict__ bq, const float* __restrict__ bk,
    const float* __restrict__ bv)
{
    extern __shared__ __align__(128) char dynsm[];
    __shared__ float bias_s[128];

    const int tid  = threadIdx.x;
    const int wid  = tid >> 5;
    const int lane = tid & 31;
    const int m0 = blockIdx.y << 7;
    const int n0 = blockIdx.x << 7;
    const int z  = blockIdx.z;
    const int wm = (wid >> 2) << 6;
    const int wn = (wid & 3) << 5;
    const int lr = lane & 15;
    const int lxh = (lane >> 4) << 4;

    const __half* A  = (z == 0) ? g_aq  : (z == 1) ? g_ak  : g_av;
    const __half* Wh = (z == 0) ? g_wqh : (z == 1) ? g_wkh : g_wvh;
    const __half* Wl = (z == 0) ? g_wql : (z == 1) ? g_wkl : g_wvl;
    const float* bias = (z == 0) ? bq : (z == 1) ? bk : bv;

    if (tid < 128) bias_s[tid] = bias[n0 + tid];

    const uint32_t sb0 = smem_u32(dynsm);
    const __half* pA  = A  + (size_t)m0 * 1024;
    const __half* pWh = Wh + (size_t)n0 * 1024;
    const __half* pWl = Wl + (size_t)n0 * 1024;

    float acc[4][4][4] = {};
    GEMM_BODY(pA, pWh, pWl)

    // epilogue: scatter [B,H,S,dk]; z=0 Q split (pre-scaled 1/8), z=1 K, z=2 V split
    const int rbase = m0 + wm + (lane >> 2);
    const int cbase = n0 + wn + ((lane & 3) << 1);
    #pragma unroll
    for (int mi = 0; mi < 4; ++mi) {
        #pragma unroll
        for (int ni = 0; ni < 4; ++ni) {
            int col = cbase + (ni << 3);
            float b0 = bias_s[col - n0], b1 = bias_s[col - n0 + 1];
            #pragma unroll
            for (int half = 0; half < 2; ++half) {
                int row = rbase + (mi << 4) + (half << 3);
                float v0 = acc[mi][ni][half*2]   + b0;
                float v1 = acc[mi][ni][half*2+1] + b1;
                int h = col >> 6, d = col & 63;
                int bb = row >> 11, s = row & 2047;
                size_t idx = ((size_t)((bb << 4) + h) * 2048 + s) * 64 + d;
                if (z == 1) {
                    *reinterpret_cast<uint32_t*>(&g_k1[idx]) = pack_h2(v0, v1);
                } else {
                    if (z == 0) { v0 *= 0.125f; v1 *= 0.125f; }
                    __half h0 = __float2half_rn(v0), h1 = __float2half_rn(v1);
                    uint32_t hi = (uint32_t)*reinterpret_cast<uint16_t*>(&h0) |
                                  ((uint32_t)*reinterpret_cast<uint16_t*>(&h1) << 16);
                    uint32_t lo = pack_h2(v0 - __half2float(h0),
                                          v1 - __half2float(h1));
                    if (z == 0) {
                        *reinterpret_cast<uint32_t*>(&g_qhi[idx]) = hi;
                        *reinterpret_cast<uint32_t*>(&g_qlo[idx]) = lo;
                    } else {
                        *reinterpret_cast<uint32_t*>(&g_vhi[idx]) = hi;
                        *reinterpret_cast<uint32_t*>(&g_vlo[idx]) = lo;
                    }
                }
            }
        }
    }
}

__global__ __launch_bounds__(256, 2) void gemm_out(
    const float* __restrict__ bo, float* __restrict__ outf)
{
    extern __shared__ __align__(128) char dynsm[];
    __shared__ float bias_s[128];

    const int tid  = threadIdx.x;
    const int wid  = tid >> 5;
    const int lane = tid & 31;
    const int m0 = blockIdx.y << 7;
    const int n0 = blockIdx.x << 7;
    const int wm = (wid >> 2) << 6;
    const int wn = (wid & 3) << 5;
    const int lr = lane & 15;
    const int lxh = (lane >> 4) << 4;

    if (tid < 128) bias_s[tid] = bo[n0 + tid];

    const uint32_t sb0 = smem_u32(dynsm);
    const __half* pA  = g_ao1 + (size_t)m0 * 1024;
    const __half* pWh = g_woh + (size_t)n0 * 1024;
    const __half* pWl = g_wol + (size_t)n0 * 1024;

    float acc[4][4][4] = {};
    GEMM_BODY(pA, pWh, pWl)

    const int rbase = m0 + wm + (lane >> 2);
    const int cbase = n0 + wn + ((lane & 3) << 1);
    #pragma unroll
    for (int mi = 0; mi < 4; ++mi)
        #pragma unroll
        for (int ni = 0; ni < 4; ++ni) {
            int col = cbase + (ni << 3);
            float b0 = bias_s[col - n0], b1 = bias_s[col - n0 + 1];
            #pragma unroll
            for (int half = 0; half < 2; ++half) {
                int row = rbase + (mi << 4) + (half << 3);
                *reinterpret_cast<float2*>(&outf[(size_t)row * 1024 + col]) =
                    make_float2(acc[mi][ni][half*2] + b0,
                                acc[mi][ni][half*2+1] + b1);
            }
        }
}

// ---------------- tensor-core flash attention (fp16 2-term) -----------------
// CTA = 64 q-rows, 128 threads, 2 CTAs/SM. Q split (regs) x K single;
// P single x V split. Mask as bits (1KB/stage).
#define ATT_KV 16384
#define ATT_MB 1024
#define ATT_STAGE (3*ATT_KV + ATT_MB)            // 50176
#define ATT_SMEM (2*ATT_STAGE)                   // 100352

__device__ __forceinline__ void att_stage(
    uint32_t sb, const __half* __restrict__ K, const __half* __restrict__ Vh,
    const __half* __restrict__ Vl, const uint32_t* __restrict__ Mb,
    int kt, int q0, int tid)
{
    #pragma unroll
    for (int i = 0; i < 8; ++i) {
        int seg = tid + (i << 7);
        int row = seg >> 3, cs = seg & 7;
        uint32_t so = row * 128 + ((cs << 4) ^ ((row & 7) << 4));
        size_t gofs = (size_t)((kt << 7) + row) * 64 + (cs << 3);
        cpa16(sb + so,            K  + gofs);
        cpa16(sb + ATT_KV + so,   Vh + gofs);
        cpa16(sb + 2*ATT_KV + so, Vl + gofs);
    }
    if (tid < 64)
        cpa16(sb + 3*ATT_KV + tid * 16,
              (const char*)(Mb + (size_t)(q0 + tid) * 64) + (kt << 4));
    CP_COMMIT();
}

__global__ __launch_bounds__(128, 2) void attn_tc()
{
    extern __shared__ __align__(128) char sm[];
    const int tid  = threadIdx.x;
    const int wid  = tid >> 5;
    const int lane = tid & 31;
    const int bh = blockIdx.y;
    const int b = bh >> 4, h = bh & 15;
    const int q0 = blockIdx.x << 6;

    const uint32_t smb = smem_u32(sm);
    const uint32_t stg[2] = {smb, smb + ATT_STAGE};

    const size_t hofs = (size_t)bh * 2048 * 64;
    const __half* gqh = g_qhi + hofs + (size_t)q0 * 64;
    const __half* gql = g_qlo + hofs + (size_t)q0 * 64;
    const __half* gk  = g_k1 + hofs;
    const __half* gvh = g_vhi + hofs;
    const __half* gvl = g_vlo + hofs;
    const uint32_t* gmb = g_mbits + (size_t)b * 2048 * 64;

    // ---- stage Q (hi, lo) through buffer 0, extract frags to registers ----
    #pragma unroll
    for (int i = 0; i < 4; ++i) {
        int seg = tid + (i << 7);
        int row = seg >> 3, cs = seg & 7;
        uint32_t so = row * 128 + ((cs << 4) ^ ((row & 7) << 4));
        size_t gofs = (size_t)row * 64 + (cs << 3);
        cpa16(smb + so,        gqh + gofs);
        cpa16(smb + 8192 + so, gql + gofs);
    }
    CP_COMMIT();
    CP_WAIT(0);
    __syncthreads();

    const int lr  = lane & 15;
    const int lxh = (lane >> 4) << 4;
    const int r   = lane >> 2;
    const int c2  = (lane & 3) << 1;

    uint32_t qh[4][4], ql[4][4];
    {
        int row = (wid << 4) + lr;
        uint32_t rb = smb + row * 128;
        uint32_t sw = (row & 7) << 4;
        #pragma unroll
        for (int kk = 0; kk < 4; ++kk) {
            uint32_t ad = rb + (((kk << 5) + lxh) ^ sw);
            LDSM4(qh[kk][0], qh[kk][1], qh[kk][2], qh[kk][3], ad);
            LDSM4(ql[kk][0], ql[kk][1], ql[kk][2], ql[kk][3], ad + 8192);
        }
    }
    __syncthreads();   // all warps done reading Q before stage 0 overwrite

    att_stage(stg[0], gk, gvh, gvl, gmb, 0, q0, tid);
    att_stage(stg[1], gk, gvh, gvl, gmb, 1, q0, tid);

    float o[8][4] = {};
    float m0 = -1e30f, m1 = -1e30f, l0 = 0.f, l1 = 0.f;
    const int qr0 = (wid << 4) + r;

    for (int kt = 0; kt < 16; ++kt) {
        if (kt < 15) { CP_WAIT(1); } else { CP_WAIT(0); }
        __syncthreads();
        const uint32_t sb = stg[kt & 1];
        const char* stp = sm + (kt & 1) * ATT_STAGE;

        // ---- S = (Qh + Ql) x K ----
        float sc[16][4];
        #pragma unroll
        for (int nt = 0; nt < 16; ++nt)
            #pragma unroll
            for (int j = 0; j < 4; ++j) sc[nt][j] = 0.f;

        #pragma unroll
        for (int g = 0; g < 8; ++g) {
            int krow = (g << 4) + lr;
            uint32_t rb = sb + krow * 128;
            uint32_t sw = (krow & 7) << 4;
            #pragma unroll
            for (int kk = 0; kk < 4; ++kk) {
                uint32_t ad = rb + (((kk << 5) + lxh) ^ sw);
                uint32_t k0r, k1r, k2r, k3r;
                LDSM4(k0r, k1r, k2r, k3r, ad);
                uint32_t bE[2] = {k0r, k2r}, bO[2] = {k1r, k3r};
                MMA16816(sc[2*g],   qh[kk], bE);
                MMA16816(sc[2*g],   ql[kk], bE);
                MMA16816(sc[2*g+1], qh[kk], bO);
                MMA16816(sc[2*g+1], ql[kk], bO);
            }
        }

        // ---- mask bits + online softmax ----
        uint4 mv0 = *reinterpret_cast<const uint4*>(stp + 3*ATT_KV + qr0 * 16);
        uint4 mv1 = *reinterpret_cast<const uint4*>(stp + 3*ATT_KV + (qr0 + 8) * 16);
        uint32_t mw0[4] = {mv0.x, mv0.y, mv0.z, mv0.w};
        uint32_t mw1[4] = {mv1.x, mv1.y, mv1.z, mv1.w};

        float mx0 = -1e30f, mx1 = -1e30f;
        #pragma unroll
        for (int nt = 0; nt < 16; ++nt) {
            uint32_t w0 = mw0[nt >> 2], w1 = mw1[nt >> 2];
            int sh = ((nt & 3) << 3) + c2;
            float v;
            v = ((w0 >> sh) & 1u)       ? sc[nt][0] : EPS_VAL; sc[nt][0] = v; mx0 = fmaxf(mx0, v);
            v = ((w0 >> (sh + 1)) & 1u) ? sc[nt][1] : EPS_VAL; sc[nt][1] = v; mx0 = fmaxf(mx0, v);
            v = ((w1 >> sh) & 1u)       ? sc[nt][2] : EPS_VAL; sc[nt][2] = v; mx1 = fmaxf(mx1, v);
            v = ((w1 >> (sh + 1)) & 1u) ? sc[nt][3] : EPS_VAL; sc[nt][3] = v; mx1 = fmaxf(mx1, v);
        }
        mx0 = fmaxf(mx0, __shfl_xor_sync(~0u, mx0, 1));
        mx0 = fmaxf(mx0, __shfl_xor_sync(~0u, mx0, 2));
        mx1 = fmaxf(mx1, __shfl_xor_sync(~0u, mx1, 1));
        mx1 = fmaxf(mx1, __shfl_xor_sync(~0u, mx1, 2));
        float mn0 = fmaxf(m0, mx0), mn1 = fmaxf(m1, mx1);
        float co0 = __expf(m0 - mn0), co1 = __expf(m1 - mn1);
        m0 = mn0; m1 = mn1;

        float rs0 = 0.f, rs1 = 0.f;
        #pragma unroll
        for (int nt = 0; nt < 16; ++nt) {
            float e;
            e = __expf(sc[nt][0] - mn0); sc[nt][0] = e; rs0 += e;
            e = __expf(sc[nt][1] - mn0); sc[nt][1] = e; rs0 += e;
            e = __expf(sc[nt][2] - mn1); sc[nt][2] = e; rs1 += e;
            e = __expf(sc[nt][3] - mn1); sc[nt][3] = e; rs1 += e;
        }
        rs0 += __shfl_xor_sync(~0u, rs0, 1); rs0 += __shfl_xor_sync(~0u, rs0, 2);
        rs1 += __shfl_xor_sync(~0u, rs1, 1); rs1 += __shfl_xor_sync(~0u, rs1, 2);
        l0 = l0 * co0 + rs0;
        l1 = l1 * co1 + rs1;
        #pragma unroll
        for (int ni = 0; ni < 8; ++ni) {
            o[ni][0] *= co0; o[ni][1] *= co0;
            o[ni][2] *= co1; o[ni][3] *= co1;
        }

        // ---- O += P x (Vh + Vl), P single fp16 ----
        #pragma unroll
        for (int t = 0; t < 8; ++t) {
            uint32_t aP[4];
            #pragma unroll
            for (int u = 0; u < 4; ++u)
                aP[u] = pack_h2(sc[2*t + (u >> 1)][(u & 1) * 2],
                                sc[2*t + (u >> 1)][(u & 1) * 2 + 1]);
            int vrow = (t << 4) + lr;
            uint32_t rb = sb + ATT_KV + vrow * 128;
            uint32_t sw = (vrow & 7) << 4;
            #pragma unroll
            for (int dp = 0; dp < 4; ++dp) {
                uint32_t ad = rb + (((dp << 5) + lxh) ^ sw);
                uint32_t h0, h1, h2, h3, L0, L1, L2, L3;
                LDSM4T(h0, h1, h2, h3, ad);
                LDSM4T(L0, L1, L2, L3, ad + ATT_KV);
                uint32_t bh0[2] = {h0, h1}, bh1[2] = {h2, h3};
                uint32_t bl0[2] = {L0, L1}, bl1[2] = {L2, L3};
                MMA16816(o[2*dp],   aP, bh0);
                MMA16816(o[2*dp],   aP, bl0);
                MMA16816(o[2*dp+1], aP, bh1);
                MMA16816(o[2*dp+1], aP, bl1);
            }
        }

        __syncthreads();
        if (kt + 2 < 16)
            att_stage(stg[kt & 1], gk, gvh, gvl, gmb, kt + 2, q0, tid);
    }

    // ---- epilogue: normalize, single fp16 store [B,S,1024] ----
    float i0 = 1.f / l0, i1 = 1.f / l1;
    int row0 = q0 + (wid << 4) + r;
    size_t base0 = ((size_t)(b * 2048) + row0) * 1024 + h * 64;
    size_t base1 = base0 + 8 * 1024;
    #pragma unroll
    for (int ni = 0; ni < 8; ++ni) {
        int d = (ni << 3) + c2;
        *reinterpret_cast<uint32_t*>(&g_ao1[base0 + d]) =
            pack_h2(o[ni][0] * i0, o[ni][1] * i0);
        *reinterpret_cast<uint32_t*>(&g_ao1[base1 + d]) =
            pack_h2(o[ni][2] * i1, o[ni][3] * i1);
    }
}

// ---------------------------------------------------------------------------
extern "C" void kernel_launch(void* const* d_in, const int* in_sizes, int n_in,
                              void* d_out, int out_size)
{
    const float* query = (const float*)d_in[0];
    const float* key_  = (const float*)d_in[1];
    const float* value = (const float*)d_in[2];
    const int*   mask  = (const int*)  d_in[3];
    const float* wq = (const float*)d_in[4];
    const float* bq = (const float*)d_in[5];
    const float* wk = (const float*)d_in[6];
    const float* bk = (const float*)d_in[7];
    const float* wv = (const float*)d_in[8];
    const float* bv = (const float*)d_in[9];
    const float* wo = (const float*)d_in[10];
    const float* bo = (const float*)d_in[11];

    void *paq, *pak, *pav, *pwqh, *pwql, *pwkh, *pwkl, *pwvh, *pwvl,
         *pwoh, *pwol, *pmb;
    cudaGetSymbolAddress(&paq,  g_aq);
    cudaGetSymbolAddress(&pak,  g_ak);
    cudaGetSymbolAddress(&pav,  g_av);
    cudaGetSymbolAddress(&pwqh, g_wqh);
    cudaGetSymbolAddress(&pwql, g_wql);
    cudaGetSymbolAddress(&pwkh, g_wkh);
    cudaGetSymbolAddress(&pwkl, g_wkl);
    cudaGetSymbolAddress(&pwvh, g_wvh);
    cudaGetSymbolAddress(&pwvl, g_wvl);
    cudaGetSymbolAddress(&pwoh, g_woh);
    cudaGetSymbolAddress(&pwol, g_wol);
    cudaGetSymbolAddress(&pmb,  g_mbits);

    cudaFuncSetAttribute(gemm_qkv,
                         cudaFuncAttributeMaxDynamicSharedMemorySize, G_SMEM);
    cudaFuncSetAttribute(gemm_out,
                         cudaFuncAttributeMaxDynamicSharedMemorySize, G_SMEM);
    cudaFuncSetAttribute(attn_tc,
                         cudaFuncAttributeMaxDynamicSharedMemorySize, ATT_SMEM);

    conv_maskbits<<<65536, 256>>>(mask, (uint32_t*)pmb);
    conv_h1<<<8192, 256>>>((const float4*)query, (uint2*)paq, 2097152);
    conv_h1<<<8192, 256>>>((const float4*)key_,  (uint2*)pak, 2097152);
    conv_h1<<<8192, 256>>>((const float4*)value, (uint2*)pav, 2097152);
    conv_hsplit<<<1024, 256>>>((const float4*)wq, (uint2*)pwqh, (uint2*)pwql, 262144);
    conv_hsplit<<<1024, 256>>>((const float4*)wk, (uint2*)pwkh, (uint2*)pwkl, 262144);
    conv_hsplit<<<1024, 256>>>((const float4*)wv, (uint2*)pwvh, (uint2*)pwvl, 262144);
    conv_hsplit<<<1024, 256>>>((const float4*)wo, (uint2*)pwoh, (uint2*)pwol, 262144);

    gemm_qkv<<<dim3(8, 64, 3), 256, G_SMEM>>>(bq, bk, bv);
    attn_tc<<<dim3(32, 64), 128, ATT_SMEM>>>();
    gemm_out<<<dim3(8, 64), 256, G_SMEM>>>(bo, (float*)d_out);
}